// round 13
// baseline (speedup 1.0000x reference)
#include <cuda_runtime.h>
#include <cuda_bf16.h>
#include <math.h>
#include <cstdint>

// ---------------- problem constants ----------------
#define BATCH 64
#define NTOK 197
#define NPATCH 196
#define EMBED 192
#define HEADS 3
#define HDIM 64
#define FEAT 256
#define MLPD 768
#define NCLS 1000
#define DEPTH 12
#define ROWS (BATCH*NTOK)          // 12608
#define BHN  (BATCH*HEADS*NTOK)    // 37824
#define VSTR 72                    // v row stride (64 data + ones col + pad)
#define ZB   (BATCH*HEADS)         // 192 batches

// ---------------- scratch (device globals) ----------------
__device__ float g_h   [ROWS*EMBED];
__device__ float g_xln [ROWS*EMBED];
__device__ float g_qkv [ROWS*3*EMBED];
__device__ float g_qk  [2L*BHN*HDIM];
__device__ float g_v   [BHN*VSTR];
__device__ float g_nrm [2L*BHN];
__device__ float g_pqk [2L*BHN*FEAT];
__device__ float g_dv  [ZB*NTOK];
__device__ float g_kvT [ZB*VSTR*FEAT];     // per batch: [72][256]; row 64 = ks
__device__ float g_ao  [ROWS*EMBED];
__device__ float g_mlp [ROWS*MLPD];
__device__ float g_pool[BATCH*EMBED];
__device__ float g_poolpart[25*BATCH*EMBED];
__device__ float g_cls [BATCH*EMBED];
// transposed weights [Npad][K] (K-major)
__device__ float g_wqkvT [DEPTH*640*192];
__device__ float g_wapT  [DEPTH*192*192];
__device__ float g_wfc1T [DEPTH*768*192];
__device__ float g_wfc2T [DEPTH*192*768];
__device__ float g_wexT  [3*1024*192];
__device__ float g_whdT  [1024*192];

__device__ __forceinline__ float warpSum(float v) {
    #pragma unroll
    for (int o = 16; o > 0; o >>= 1) v += __shfl_xor_sync(0xffffffffu, v, o);
    return v;
}

// =====================================================================
// bf16x3 mma GEMM: C[M,Nreal] = A[M,K] @ Bt^T  (optional batch over z)
// Bt stored [n][k] row-major. Split once into smem.
// BNv: 128 or 64.  EPI: 0=bias, 1=bias+gelu, 2=bias+residual,
//   3=dinv-scale + head scatter (batched attention out),
//   4=exp(acc - rowSumSq(A)/2)*64^-0.25
// =====================================================================
#define MMA_BF16(d, a, b) \
  asm volatile("mma.sync.aligned.m16n8k16.row.col.f32.bf16.bf16.f32 " \
    "{%0,%1,%2,%3}, {%4,%5,%6,%7}, {%8,%9}, {%0,%1,%2,%3};" \
    : "+f"((d)[0]), "+f"((d)[1]), "+f"((d)[2]), "+f"((d)[3]) \
    : "r"((a)[0]), "r"((a)[1]), "r"((a)[2]), "r"((a)[3]), \
      "r"((b)[0]), "r"((b)[1]))

#define PACK_BF2(w, flo, fhi) \
  asm("cvt.rn.bf16x2.f32 %0, %1, %2;" : "=r"(w) : "f"(fhi), "f"(flo))

__device__ __forceinline__ void split_pair(float x0, float x1,
                                           uint32_t& h, uint32_t& l) {
    PACK_BF2(h, x0, x1);
    float h0 = __uint_as_float(h << 16);
    float h1 = __uint_as_float(h & 0xffff0000u);
    PACK_BF2(l, x0 - h0, x1 - h1);
}

#define B3_ROW 20
#define A_TILE (128*B3_ROW)
template<int BNv> struct SmemSz {
    static constexpr int BT = BNv * B3_ROW;
    static constexpr int BYTES = (4 * A_TILE + 4 * BT) * 4;
};

template<int EPI, int BNv>
__global__ __launch_bounds__(256, 2)
void bf3_gemm(const float* __restrict__ A, const float* __restrict__ Bt,
              const float* __restrict__ bias, const float* __restrict__ res,
              const float* __restrict__ aux, float* __restrict__ C,
              int M, int Nreal, int K, long bRows, long sA, long sBt)
{
    constexpr int NT = BNv / 16;
    constexpr int BT = BNv * B3_ROW;
    extern __shared__ uint32_t smu[];
    uint32_t* Abase = smu;
    uint32_t* Bbase = smu + 4 * A_TILE;

    int z = blockIdx.z;
    const float* Ab  = A  + (long)z * sA;
    const float* Btb = Bt + (long)z * sBt;

    int tid = threadIdx.x;
    int lane = tid & 31, wid = tid >> 5;
    int wm = (wid & 3) * 32;
    int wn = (wid >> 2) * (BNv / 2);
    int mBase = blockIdx.y * 128, nBase = blockIdx.x * BNv;

    float acc[2][NT][4];
    #pragma unroll
    for (int mt = 0; mt < 2; mt++)
        #pragma unroll
        for (int nt = 0; nt < NT; nt++)
            #pragma unroll
            for (int q = 0; q < 4; q++) acc[mt][nt][q] = 0.f;

    auto ldA = [&](uint32_t* dhi, uint32_t* dlo, int k0) {
        int r = tid >> 1, half = tid & 1;
        long gr = (long)mBase + r;
        float f[16];
        if (gr < M) {
            const float4* src = (const float4*)(Ab + gr * (long)K + k0 + half * 16);
            #pragma unroll
            for (int u = 0; u < 4; u++) {
                float4 v = src[u];
                f[4*u] = v.x; f[4*u+1] = v.y; f[4*u+2] = v.z; f[4*u+3] = v.w;
            }
        } else {
            #pragma unroll
            for (int u = 0; u < 16; u++) f[u] = 0.f;
        }
        uint32_t hw[8], lw[8];
        #pragma unroll
        for (int p = 0; p < 8; p++) split_pair(f[2*p], f[2*p+1], hw[p], lw[p]);
        uint32_t* ph = dhi + r * B3_ROW + half * 8;
        uint32_t* pl = dlo + r * B3_ROW + half * 8;
        *(uint4*)ph       = make_uint4(hw[0], hw[1], hw[2], hw[3]);
        *(uint4*)(ph + 4) = make_uint4(hw[4], hw[5], hw[6], hw[7]);
        *(uint4*)pl       = make_uint4(lw[0], lw[1], lw[2], lw[3]);
        *(uint4*)(pl + 4) = make_uint4(lw[4], lw[5], lw[6], lw[7]);
    };

    auto ldB = [&](uint32_t* dhi, uint32_t* dlo, int k0) {
        if (BNv == 128) {
            int r = tid >> 1, half = tid & 1;
            long gr = (long)nBase + r;
            float f[16];
            if (gr < bRows) {
                const float4* src = (const float4*)(Btb + gr * (long)K + k0 + half * 16);
                #pragma unroll
                for (int u = 0; u < 4; u++) {
                    float4 v = src[u];
                    f[4*u] = v.x; f[4*u+1] = v.y; f[4*u+2] = v.z; f[4*u+3] = v.w;
                }
            } else {
                #pragma unroll
                for (int u = 0; u < 16; u++) f[u] = 0.f;
            }
            uint32_t hw[8], lw[8];
            #pragma unroll
            for (int p = 0; p < 8; p++) split_pair(f[2*p], f[2*p+1], hw[p], lw[p]);
            uint32_t* ph = dhi + r * B3_ROW + half * 8;
            uint32_t* pl = dlo + r * B3_ROW + half * 8;
            *(uint4*)ph       = make_uint4(hw[0], hw[1], hw[2], hw[3]);
            *(uint4*)(ph + 4) = make_uint4(hw[4], hw[5], hw[6], hw[7]);
            *(uint4*)pl       = make_uint4(lw[0], lw[1], lw[2], lw[3]);
            *(uint4*)(pl + 4) = make_uint4(lw[4], lw[5], lw[6], lw[7]);
        } else {
            int r = tid >> 2, q = tid & 3;
            long gr = (long)nBase + r;
            float f[8];
            if (gr < bRows) {
                const float4* src = (const float4*)(Btb + gr * (long)K + k0 + q * 8);
                float4 v0 = src[0], v1 = src[1];
                f[0]=v0.x; f[1]=v0.y; f[2]=v0.z; f[3]=v0.w;
                f[4]=v1.x; f[5]=v1.y; f[6]=v1.z; f[7]=v1.w;
            } else {
                #pragma unroll
                for (int u = 0; u < 8; u++) f[u] = 0.f;
            }
            uint32_t hw[4], lw[4];
            #pragma unroll
            for (int p = 0; p < 4; p++) split_pair(f[2*p], f[2*p+1], hw[p], lw[p]);
            *(uint4*)(dhi + r * B3_ROW + q * 4) = make_uint4(hw[0], hw[1], hw[2], hw[3]);
            *(uint4*)(dlo + r * B3_ROW + q * 4) = make_uint4(lw[0], lw[1], lw[2], lw[3]);
        }
    };

    __shared__ float snrm[128];
    if (EPI == 4) {   // per-row sumsq/2 (K == 64 for fmap)
        int r = tid >> 1, half = tid & 1;
        long gr = (long)mBase + r;
        float ss = 0.f;
        if (gr < M) {
            const float4* src = (const float4*)(Ab + gr * (long)K + half * 32);
            #pragma unroll
            for (int u = 0; u < 8; u++) {
                float4 vv = src[u];
                ss += vv.x * vv.x + vv.y * vv.y + vv.z * vv.z + vv.w * vv.w;
            }
        }
        ss += __shfl_xor_sync(0xffffffffu, ss, 1);
        if (half == 0) snrm[r] = ss * 0.5f;
    }

    ldA(Abase, Abase + A_TILE, 0);
    ldB(Bbase, Bbase + BT, 0);
    __syncthreads();

    int nSteps = K / 32;
    for (int s = 0; s < nSteps; s++) {
        int buf = s & 1;
        if (s + 1 < nSteps) {
            int nb = buf ^ 1;
            ldA(Abase + nb * 2 * A_TILE, Abase + nb * 2 * A_TILE + A_TILE, (s + 1) * 32);
            ldB(Bbase + nb * 2 * BT,     Bbase + nb * 2 * BT + BT,         (s + 1) * 32);
        }
        const uint32_t* Ah = Abase + buf * 2 * A_TILE;
        const uint32_t* Al = Ah + A_TILE;
        const uint32_t* Bh = Bbase + buf * 2 * BT;
        const uint32_t* Bl = Bh + BT;
        #pragma unroll
        for (int h16 = 0; h16 < 2; h16++) {
            int wb = h16 * 8 + (lane & 3);
            uint32_t ah[2][4], al[2][4];
            #pragma unroll
            for (int mt = 0; mt < 2; mt++) {
                int r0 = (wm + mt * 16 + (lane >> 2)) * B3_ROW + wb;
                ah[mt][0] = Ah[r0];
                ah[mt][1] = Ah[r0 + 8 * B3_ROW];
                ah[mt][2] = Ah[r0 + 4];
                ah[mt][3] = Ah[r0 + 8 * B3_ROW + 4];
                al[mt][0] = Al[r0];
                al[mt][1] = Al[r0 + 8 * B3_ROW];
                al[mt][2] = Al[r0 + 4];
                al[mt][3] = Al[r0 + 8 * B3_ROW + 4];
            }
            #pragma unroll
            for (int nt = 0; nt < NT; nt++) {
                int rb = (wn + nt * 8 + (lane >> 2)) * B3_ROW + wb;
                uint32_t bh[2] = { Bh[rb], Bh[rb + 4] };
                uint32_t bl[2] = { Bl[rb], Bl[rb + 4] };
                #pragma unroll
                for (int mt = 0; mt < 2; mt++) {
                    MMA_BF16(acc[mt][nt], ah[mt], bh);
                    MMA_BF16(acc[mt][nt], ah[mt], bl);
                    MMA_BF16(acc[mt][nt], al[mt], bh);
                }
            }
        }
        __syncthreads();
    }

    // ---- epilogue ----
    #pragma unroll
    for (int mt = 0; mt < 2; mt++) {
        int r0loc = wm + mt * 16 + (lane >> 2);
        #pragma unroll
        for (int e = 0; e < 2; e++) {
            int rowLoc = r0loc + e * 8;
            int row = mBase + rowLoc;
            if (row >= M) continue;
            if (EPI == 3) {
                // batched attention-out: scale by dinv, scatter to [B,N,EMBED]
                int bb = z / 3, hh = z % 3;
                float dvv = aux[(long)z * NTOK + row];
                float* Cp = C + ((long)bb * NTOK + row) * EMBED + hh * HDIM;
                #pragma unroll
                for (int nt = 0; nt < NT; nt++) {
                    int c0 = nBase + wn + nt * 8 + 2 * (lane & 3);
                    #pragma unroll
                    for (int q = 0; q < 2; q++) {
                        int col = c0 + q;
                        if (col < Nreal) Cp[col] = acc[mt][nt][e * 2 + q] * dvv;
                    }
                }
            } else {
                float auxv = (EPI == 4) ? snrm[rowLoc] : 0.f;
                float* Cp = C + (long)row * Nreal;
                const float* Rp = (EPI == 2) ? res + (long)row * Nreal : nullptr;
                #pragma unroll
                for (int nt = 0; nt < NT; nt++) {
                    int c0 = nBase + wn + nt * 8 + 2 * (lane & 3);
                    #pragma unroll
                    for (int q = 0; q < 2; q++) {
                        int col = c0 + q;
                        if (col >= Nreal) continue;
                        float v = acc[mt][nt][e * 2 + q];
                        if (EPI == 4) {
                            v = __expf(v - auxv) * 0.35355339059327373f;
                        } else {
                            v += bias[col];
                            if (EPI == 1) v = 0.5f * v * (1.0f + erff(v * 0.70710678118654752f));
                            if (EPI == 2) v += Rp[col];
                        }
                        Cp[col] = v;
                    }
                }
            }
        }
    }
}

// ---------------- weight transpose+pad ----------------
__global__ void transp_k(const float* __restrict__ in, float* __restrict__ out,
                         int K, int N, int Npad)
{
    int z = blockIdx.y;
    long idx = (long)blockIdx.x * 256 + threadIdx.x;
    if (idx >= (long)Npad * K) return;
    int n = (int)(idx / K), k = (int)(idx % K);
    out[(long)z * Npad * K + idx] =
        (n < N) ? in[(long)z * K * N + (long)k * N + n] : 0.f;
}

// ---------------- SIMT FFMA2 GEMM: kv_aug = pk^T @ [v|1], writes kvT ----
#define FMA2(acc, a, b) asm("fma.rn.f32x2 %0, %1, %2, %0;" : "+l"(acc) : "l"(a), "l"(b))
#define PACK2(dst, s)   asm("mov.b64 %0, {%1, %1};" : "=l"(dst) : "f"(s))
#define BKq 16

// TA GEMM, C written transposed: C[col*M + row] (per batch z)
__global__ __launch_bounds__(128, 3)
void kv_gemm(const float* __restrict__ A, const float* __restrict__ Bm,
             float* __restrict__ C, int M, int N, int K,
             long sA, long sB, long sC)
{
    constexpr int BMv = 128, BNv = 64, THREADS = 128, CT = 8;
    __shared__ __align__(16) float As[2][BKq][BMv + 4];
    __shared__ __align__(16) float Bs[2][BKq][BNv + 4];

    int z = blockIdx.z;
    const float* Ab = A + (long)z * sA;
    const float* Bb = Bm + (long)z * sB;
    int mBase = blockIdx.y * BMv;
    int nBase = blockIdx.x * BNv;
    int tid = threadIdx.x;
    int rt = tid / CT, ct = tid % CT;

    unsigned long long acc[8][4];
    #pragma unroll
    for (int i = 0; i < 8; i++)
        #pragma unroll
        for (int j = 0; j < 4; j++) acc[i][j] = 0ULL;

    auto loadTile = [&](int buf, int k0) {
        {   // A stored [K][M] (TA)
            #pragma unroll
            for (int f = 0; f < 4; f++) {
                int l = tid + f * THREADS;
                int kk = l / (BMv / 4);
                int m4 = (l % (BMv / 4)) * 4;
                int gk = k0 + kk;
                float4 v = make_float4(0.f, 0.f, 0.f, 0.f);
                if (gk < K) {
                    float t[4];
                    #pragma unroll
                    for (int u = 0; u < 4; u++)
                        t[u] = (mBase + m4 + u < M) ? Ab[(long)gk * M + mBase + m4 + u] : 0.f;
                    v = make_float4(t[0], t[1], t[2], t[3]);
                }
                *(float4*)&As[buf][kk][m4] = v;
            }
        }
        {   // B stored [K][N]
            #pragma unroll
            for (int f = 0; f < 2; f++) {
                int l = tid + f * THREADS;
                int kk = l / (BNv / 4);
                int n4 = (l % (BNv / 4)) * 4;
                int gk = k0 + kk;
                float4 v = make_float4(0.f, 0.f, 0.f, 0.f);
                if (gk < K) {
                    if (nBase + n4 + 3 < N) {
                        v = *(const float4*)(Bb + (long)gk * N + nBase + n4);
                    } else {
                        float t[4];
                        #pragma unroll
                        for (int u = 0; u < 4; u++)
                            t[u] = (nBase + n4 + u < N) ? Bb[(long)gk * N + nBase + n4 + u] : 0.f;
                        v = make_float4(t[0], t[1], t[2], t[3]);
                    }
                }
                *(float4*)&Bs[buf][kk][n4] = v;
            }
        }
    };

    int buf = 0;
    loadTile(0, 0);
    __syncthreads();
    for (int k0 = 0; k0 < K; k0 += BKq) {
        if (k0 + BKq < K) loadTile(buf ^ 1, k0 + BKq);
        #pragma unroll
        for (int kk = 0; kk < BKq; kk++) {
            float4 a0 = *(const float4*)&As[buf][kk][rt * 8];
            float4 a1 = *(const float4*)&As[buf][kk][rt * 8 + 4];
            ulonglong2 b0 = *(const ulonglong2*)&Bs[buf][kk][ct * 8];
            ulonglong2 b1 = *(const ulonglong2*)&Bs[buf][kk][ct * 8 + 4];
            unsigned long long bp[4] = {b0.x, b0.y, b1.x, b1.y};
            float av[8] = {a0.x, a0.y, a0.z, a0.w, a1.x, a1.y, a1.z, a1.w};
            unsigned long long ap[8];
            #pragma unroll
            for (int i = 0; i < 8; i++) PACK2(ap[i], av[i]);
            #pragma unroll
            for (int i = 0; i < 8; i++)
                #pragma unroll
                for (int j = 0; j < 4; j++)
                    FMA2(acc[i][j], ap[i], bp[j]);
        }
        __syncthreads();
        buf ^= 1;
    }

    union F2 { unsigned long long u; float2 f; };
    float* Cp = C + (long)z * sC;
    #pragma unroll
    for (int i = 0; i < 8; i++) {
        int row = mBase + rt * 8 + i;
        if (row >= M) continue;
        #pragma unroll
        for (int j = 0; j < 4; j++) {
            int cb = nBase + ct * 8 + 2 * j;
            F2 t; t.u = acc[i][j];
            if (cb < N)     Cp[(long)cb * M + row]       = t.f.x;
            if (cb + 1 < N) Cp[(long)(cb + 1) * M + row] = t.f.y;
        }
    }
}

// ---------------- LayerNorm (warp per row) ----------------
__global__ __launch_bounds__(256)
void ln_k(const float* __restrict__ in, long rowStride,
          const float* __restrict__ w, const float* __restrict__ b,
          float* __restrict__ out, int nRows)
{
    int warp = (blockIdx.x * 256 + threadIdx.x) >> 5;
    int lane = threadIdx.x & 31;
    if (warp >= nRows) return;
    const float* ip = in + (long)warp * rowStride;
    float2 v[3];
    #pragma unroll
    for (int j = 0; j < 3; j++)
        v[j] = *(const float2*)(ip + j * 64 + lane * 2);
    float s = v[0].x + v[0].y + v[1].x + v[1].y + v[2].x + v[2].y;
    float mu = warpSum(s) * (1.f / EMBED);
    float q = 0.f;
    #pragma unroll
    for (int j = 0; j < 3; j++) {
        v[j].x -= mu; v[j].y -= mu;
        q += v[j].x * v[j].x + v[j].y * v[j].y;
    }
    float rstd = rsqrtf(warpSum(q) * (1.f / EMBED) + 1e-5f);
    float* op = out + (long)warp * EMBED;
    #pragma unroll
    for (int j = 0; j < 3; j++) {
        int c = j * 64 + lane * 2;
        float2 wv = *(const float2*)(w + c);
        float2 bv = *(const float2*)(b + c);
        float2 o = make_float2(v[j].x * rstd * wv.x + bv.x,
                               v[j].y * rstd * wv.y + bv.y);
        *(float2*)(op + c) = o;
    }
}

__global__ __launch_bounds__(256)
void lnpos_k(const float* __restrict__ tok, const float* __restrict__ w,
             const float* __restrict__ b, const float* __restrict__ pos,
             float* __restrict__ h)
{
    int warp = (blockIdx.x * 256 + threadIdx.x) >> 5;
    int lane = threadIdx.x & 31;
    if (warp >= NPATCH * BATCH) return;
    int bb = warp / NPATCH, p = warp % NPATCH;
    const float* ip = tok + (long)warp * EMBED;
    float2 v[3];
    #pragma unroll
    for (int j = 0; j < 3; j++)
        v[j] = *(const float2*)(ip + j * 64 + lane * 2);
    float s = v[0].x + v[0].y + v[1].x + v[1].y + v[2].x + v[2].y;
    float mu = warpSum(s) * (1.f / EMBED);
    float q = 0.f;
    #pragma unroll
    for (int j = 0; j < 3; j++) {
        v[j].x -= mu; v[j].y -= mu;
        q += v[j].x * v[j].x + v[j].y * v[j].y;
    }
    float rstd = rsqrtf(warpSum(q) * (1.f / EMBED) + 1e-5f);
    float* op = h + ((long)bb * NTOK + 1 + p) * EMBED;
    const float* pp = pos + (1 + p) * EMBED;
    #pragma unroll
    for (int j = 0; j < 3; j++) {
        int c = j * 64 + lane * 2;
        float2 wv = *(const float2*)(w + c);
        float2 bv = *(const float2*)(b + c);
        float2 pv = *(const float2*)(pp + c);
        float2 o = make_float2(v[j].x * rstd * wv.x + bv.x + pv.x,
                               v[j].y * rstd * wv.y + bv.y + pv.y);
        *(float2*)(op + c) = o;
    }
}

__global__ void im2col_k(const float* __restrict__ x, float* __restrict__ px)
{
    long idx = (long)blockIdx.x * 256 + threadIdx.x;
    if (idx >= (long)NPATCH * BATCH * 768) return;
    int t = (int)(idx % 768);
    long rp = idx / 768;
    int b = (int)(rp / NPATCH), p = (int)(rp % NPATCH);
    int c = t >> 8, rem = t & 255, r = rem >> 4, col = rem & 15;
    int gy = p / 14, gx = p % 14;
    px[idx] = x[(((long)b * 3 + c) * 224 + gy * 16 + r) * 224 + gx * 16 + col];
}

__global__ void cls_k(const float* __restrict__ cls, const float* __restrict__ pos,
                      float* __restrict__ h)
{
    int b = blockIdx.x; int e = threadIdx.x;
    h[(long)b * NTOK * EMBED + e] = cls[e] + pos[e];
}

// ---------------- split: warp per (row, head); v gets ones column ------
__global__ __launch_bounds__(192)
void split_k(const float* __restrict__ qkv, float* __restrict__ qk,
             float* __restrict__ v, float* __restrict__ nrm)
{
    int wid = threadIdx.x >> 5;
    int lane = threadIdx.x & 31;
    int row = blockIdx.x * 2 + wid / 3;
    if (row >= ROWS) return;
    int hh = wid % 3;
    int b = row / NTOK, n = row % NTOK;
    const float* base = qkv + (long)row * 576 + hh * 64 + lane * 2;
    float2 qv = *(const float2*)base;
    float2 kv = *(const float2*)(base + 192);
    float2 vv = *(const float2*)(base + 384);
    long r = ((long)b * 3 + hh) * NTOK + n;
    long o = r * 64 + lane * 2;
    *(float2*)(qk + o) = qv;
    *(float2*)(qk + (long)BHN * HDIM + o) = kv;
    long o72 = r * VSTR + lane * 2;
    *(float2*)(v + o72) = vv;
    if (lane == 0) {   // ones column + zero pad
        *(float4*)(v + r * VSTR + 64) = make_float4(1.f, 0.f, 0.f, 0.f);
        *(float4*)(v + r * VSTR + 68) = make_float4(0.f, 0.f, 0.f, 0.f);
    }
    float sq = warpSum(qv.x * qv.x + qv.y * qv.y);
    float sk = warpSum(kv.x * kv.x + kv.y * kv.y);
    if (lane == 0) {
        nrm[r]       = sq * 0.5f;
        nrm[BHN + r] = sk * 0.5f;
    }
}

// ---------------- D_inv: dv = 1 / (pq . ks), ks = kvT row 64 ----------
__global__ __launch_bounds__(256)
void dinv_k(const float* __restrict__ pq, const float* __restrict__ kvT,
            float* __restrict__ dv)
{
    __shared__ float s[FEAT];
    int z = blockIdx.x;
    int tid = threadIdx.x;
    s[tid] = kvT[(long)z * VSTR * FEAT + 64 * FEAT + tid];
    __syncthreads();
    int w = tid >> 5, l = tid & 31;
    int n = blockIdx.y * 8 + w;
    if (n < NTOK) {
        const float* p = pq + ((long)z * NTOK + n) * FEAT;
        float acc = 0.f;
        #pragma unroll
        for (int f = 0; f < FEAT / 32; f++) acc += p[l + f * 32] * s[l + f * 32];
        acc = warpSum(acc);
        if (l == 0) dv[(long)z * NTOK + n] = 1.f / acc;
    }
}

// ---------------- pool 2-pass ----------------
__global__ void pool1_k(const float* __restrict__ h, float* __restrict__ part)
{
    int b = blockIdx.x, chunk = blockIdx.y, e = threadIdx.x;
    int n0 = chunk * 8;
    int n1 = n0 + 8; if (n1 > NTOK) n1 = NTOK;
    float s = 0.f;
    for (int n = n0; n < n1; n++) s += h[((long)b * NTOK + n) * EMBED + e];
    part[((long)chunk * BATCH + b) * EMBED + e] = s;
}
__global__ void pool2_k(const float* __restrict__ part, float* __restrict__ pool)
{
    int b = blockIdx.x, e = threadIdx.x;
    float s = 0.f;
    #pragma unroll
    for (int c = 0; c < 25; c++)
        s += part[((long)c * BATCH + b) * EMBED + e];
    pool[(long)b * EMBED + e] = s * (1.f / 197.f);
}

// ---------------- host launch ----------------
extern "C" void kernel_launch(void* const* d_in, const int* in_sizes, int n_in,
                              void* d_out, int out_size)
{
    const float* x            = (const float*)d_in[0];
    const float* patch_w      = (const float*)d_in[1];
    const float* patch_b      = (const float*)d_in[2];
    const float* pe_norm_w    = (const float*)d_in[3];
    const float* pe_norm_b    = (const float*)d_in[4];
    const float* cls_token    = (const float*)d_in[5];
    const float* pos_embed    = (const float*)d_in[6];
    const float* norm1_w      = (const float*)d_in[7];
    const float* norm1_b      = (const float*)d_in[8];
    const float* qkv_w        = (const float*)d_in[9];
    const float* qkv_b        = (const float*)d_in[10];
    const float* proj_mat     = (const float*)d_in[11];
    const float* attn_proj_w  = (const float*)d_in[12];
    const float* attn_proj_b  = (const float*)d_in[13];
    const float* norm2_w      = (const float*)d_in[14];
    const float* norm2_b      = (const float*)d_in[15];
    const float* fc1_w        = (const float*)d_in[16];
    const float* fc1_b        = (const float*)d_in[17];
    const float* fc2_w        = (const float*)d_in[18];
    const float* fc2_b        = (const float*)d_in[19];
    const float* exit_w       = (const float*)d_in[20];
    const float* exit_b       = (const float*)d_in[21];
    const float* final_norm_w = (const float*)d_in[22];
    const float* final_norm_b = (const float*)d_in[23];
    const float* head_w       = (const float*)d_in[24];
    const float* head_b       = (const float*)d_in[25];
    float* out = (float*)d_out;

    float *h, *xln, *qkv, *qk, *v, *nrm, *pqk, *dv, *kvT, *ao, *mlp;
    float *pool, *poolpart, *cls;
    float *wqkvT, *wapT, *wfc1T, *wfc2T, *wexT, *whdT;
    cudaGetSymbolAddress((void**)&h,    g_h);
    cudaGetSymbolAddress((void**)&xln,  g_xln);
    cudaGetSymbolAddress((void**)&qkv,  g_qkv);
    cudaGetSymbolAddress((void**)&qk,   g_qk);
    cudaGetSymbolAddress((void**)&v,    g_v);
    cudaGetSymbolAddress((void**)&nrm,  g_nrm);
    cudaGetSymbolAddress((void**)&pqk,  g_pqk);
    cudaGetSymbolAddress((void**)&dv,   g_dv);
    cudaGetSymbolAddress((void**)&kvT,  g_kvT);
    cudaGetSymbolAddress((void**)&ao,   g_ao);
    cudaGetSymbolAddress((void**)&mlp,  g_mlp);
    cudaGetSymbolAddress((void**)&pool, g_pool);
    cudaGetSymbolAddress((void**)&poolpart, g_poolpart);
    cudaGetSymbolAddress((void**)&cls,  g_cls);
    cudaGetSymbolAddress((void**)&wqkvT, g_wqkvT);
    cudaGetSymbolAddress((void**)&wapT,  g_wapT);
    cudaGetSymbolAddress((void**)&wfc1T, g_wfc1T);
    cudaGetSymbolAddress((void**)&wfc2T, g_wfc2T);
    cudaGetSymbolAddress((void**)&wexT,  g_wexT);
    cudaGetSymbolAddress((void**)&whdT,  g_whdT);

    constexpr int SM128 = SmemSz<128>::BYTES;
    constexpr int SM64  = SmemSz<64>::BYTES;
    cudaFuncSetAttribute(bf3_gemm<0,128>, cudaFuncAttributeMaxDynamicSharedMemorySize, SM128);
    cudaFuncSetAttribute(bf3_gemm<1,128>, cudaFuncAttributeMaxDynamicSharedMemorySize, SM128);
    cudaFuncSetAttribute(bf3_gemm<4,128>, cudaFuncAttributeMaxDynamicSharedMemorySize, SM128);
    cudaFuncSetAttribute(bf3_gemm<0,64>,  cudaFuncAttributeMaxDynamicSharedMemorySize, SM64);
    cudaFuncSetAttribute(bf3_gemm<2,64>,  cudaFuncAttributeMaxDynamicSharedMemorySize, SM64);
    cudaFuncSetAttribute(bf3_gemm<3,64>,  cudaFuncAttributeMaxDynamicSharedMemorySize, SM64);

    const float* pk = pqk + (long)BHN * FEAT;

    // ---- weight transposes ----
    transp_k<<<dim3((640*192 + 255)/256, DEPTH), 256>>>(qkv_w, wqkvT, 192, 576, 640);
    transp_k<<<dim3((192*192 + 255)/256, DEPTH), 256>>>(attn_proj_w, wapT, 192, 192, 192);
    transp_k<<<dim3((768*192 + 255)/256, DEPTH), 256>>>(fc1_w, wfc1T, 192, 768, 768);
    transp_k<<<dim3((192*768 + 255)/256, DEPTH), 256>>>(fc2_w, wfc2T, 768, 192, 192);
    transp_k<<<dim3((1024*192 + 255)/256, 3), 256>>>(exit_w, wexT, 192, 1000, 1024);
    transp_k<<<dim3((1024*192 + 255)/256, 1), 256>>>(head_w, whdT, 192, 1000, 1024);

    // ---- patch embed ----
    cls_k<<<BATCH, EMBED>>>(cls_token, pos_embed, h);
    im2col_k<<<(int)(((long)NPATCH * BATCH * 768 + 255) / 256), 256>>>(x, mlp);
    bf3_gemm<0,64><<<dim3(3, 98), 256, SM64>>>(
        mlp, patch_w, patch_b, nullptr, nullptr, ao,
        NPATCH * BATCH, EMBED, 768, 192, 0, 0);
    lnpos_k<<<(NPATCH * BATCH * 32 + 255) / 256, 256>>>(
        ao, pe_norm_w, pe_norm_b, pos_embed, h);

    int lnBlocks = (ROWS * 32 + 255) / 256;
    for (int i = 0; i < DEPTH; i++) {
        ln_k<<<lnBlocks, 256>>>(h, EMBED, norm1_w + i * EMBED, norm1_b + i * EMBED,
                                xln, ROWS);
        // qkv (BN128; N=576 pad 640)
        bf3_gemm<0,128><<<dim3(5, 99), 256, SM128>>>(
            xln, wqkvT + (long)i * 640 * 192, qkv_b + i * 3 * EMBED,
            nullptr, nullptr, qkv, ROWS, 3 * EMBED, EMBED, 640, 0, 0);
        split_k<<<(ROWS + 1) / 2, 192>>>(qkv, qk, v, nrm);
        // feature maps (BN128; N=256 exact)
        bf3_gemm<4,128><<<dim3(2, 591), 256, SM128>>>(
            qk, proj_mat + (long)i * FEAT * HDIM, nullptr, nullptr, nrm, pqk,
            2 * BHN, FEAT, HDIM, FEAT, 0, 0);
        // kv_aug = pk^T @ [v|1]  -> kvT [72][256] per batch (row 64 = ks)
        kv_gemm<<<dim3(2, 2, ZB), 128>>>(
            pk, v, kvT, FEAT, VSTR, NTOK,
            (long)NTOK * FEAT, (long)NTOK * VSTR, (long)VSTR * FEAT);
        dinv_k<<<dim3(ZB, 25), 256>>>(pqk, kvT, dv);
        // ao = (pq @ kv) * D_inv  (bf3, batched, BN64)
        bf3_gemm<3,64><<<dim3(1, 2, ZB), 256, SM64>>>(
            pqk, kvT, nullptr, nullptr, dv, ao,
            NTOK, HDIM, FEAT, HDIM, (long)NTOK * FEAT, (long)VSTR * FEAT);
        // attn proj + residual (BN64, exact N=192)
        bf3_gemm<2,64><<<dim3(3, 99), 256, SM64>>>(
            ao, wapT + (long)i * 192 * 192, attn_proj_b + i * EMBED,
            h, nullptr, h, ROWS, EMBED, EMBED, 192, 0, 0);
        ln_k<<<lnBlocks, 256>>>(h, EMBED, norm2_w + i * EMBED, norm2_b + i * EMBED,
                                xln, ROWS);
        // MLP
        bf3_gemm<1,128><<<dim3(6, 99), 256, SM128>>>(
            xln, wfc1T + (long)i * 768 * 192, fc1_b + i * MLPD,
            nullptr, nullptr, mlp, ROWS, MLPD, EMBED, 768, 0, 0);
        bf3_gemm<2,64><<<dim3(3, 99), 256, SM64>>>(
            mlp, wfc2T + (long)i * 192 * 768, fc2_b + i * EMBED,
            h, nullptr, h, ROWS, EMBED, MLPD, 192, 0, 0);
        if (i == 3 || i == 7 || i == 11) {
            int e = (i == 3) ? 0 : (i == 7) ? 1 : 2;
            pool1_k<<<dim3(BATCH, 25), EMBED>>>(h, poolpart);
            pool2_k<<<BATCH, EMBED>>>(poolpart, pool);
            bf3_gemm<0,128><<<dim3(8, 1), 256, SM128>>>(
                pool, wexT + (long)e * 1024 * 192, exit_b + e * NCLS,
                nullptr, nullptr, out + (long)(1 + e) * BATCH * NCLS,
                BATCH, NCLS, EMBED, 1024, 0, 0);
        }
    }

    ln_k<<<(BATCH * 32 + 255) / 256, 256>>>(
        h, (long)NTOK * EMBED, final_norm_w, final_norm_b, cls, BATCH);
    bf3_gemm<0,128><<<dim3(8, 1), 256, SM128>>>(
        cls, whdT, head_b, nullptr, nullptr, out, BATCH, NCLS, EMBED, 1024, 0, 0);
}

// round 14
// speedup vs baseline: 1.0623x; 1.0623x over previous
#include <cuda_runtime.h>
#include <cuda_bf16.h>
#include <math.h>
#include <cstdint>

// ---------------- problem constants ----------------
#define BATCH 64
#define NTOK 197
#define NPATCH 196
#define EMBED 192
#define HEADS 3
#define HDIM 64
#define FEAT 256
#define MLPD 768
#define NCLS 1000
#define DEPTH 12
#define ROWS (BATCH*NTOK)          // 12608
#define BHN  (BATCH*HEADS*NTOK)    // 37824

// ---------------- scratch (device globals) ----------------
__device__ float g_h   [ROWS*EMBED];
__device__ float g_xln [ROWS*EMBED];
__device__ float g_qkv [ROWS*3*EMBED];
__device__ float g_qk  [2L*BHN*HDIM];
__device__ float g_v   [BHN*HDIM];
__device__ float g_nrm [2L*BHN];
__device__ float g_pqk [2L*BHN*FEAT];
__device__ float g_ks  [BATCH*HEADS*FEAT];
__device__ float g_kspart [7*BATCH*HEADS*FEAT];
__device__ float g_dv  [BATCH*HEADS*NTOK];
__device__ float g_kv  [BATCH*HEADS*FEAT*HDIM];
__device__ float g_ao  [ROWS*EMBED];
__device__ float g_mlp [ROWS*MLPD];
__device__ float g_pool[BATCH*EMBED];
__device__ float g_poolpart[25*BATCH*EMBED];
__device__ float g_cls [BATCH*EMBED];
// transposed weights [Npad][K] (K-major)
__device__ float g_wqkvT [DEPTH*576*192];
__device__ float g_wapT  [DEPTH*192*192];
__device__ float g_wfc1T [DEPTH*768*192];
__device__ float g_wfc2T [DEPTH*192*768];
__device__ float g_wexT  [3*1024*192];
__device__ float g_whdT  [1024*192];

__device__ __forceinline__ float warpSum(float v) {
    #pragma unroll
    for (int o = 16; o > 0; o >>= 1) v += __shfl_xor_sync(0xffffffffu, v, o);
    return v;
}

// =====================================================================
// bf16x3 mma GEMM: C[M,Nreal] = A[M,K] @ Bt^T
// Bt stored [n][k] row-major. Split once into smem:
// hi = bf16(x), lo = bf16(x - hi); acc += hi*hi + hi*lo + lo*hi.
// BNv: 128 (warp tile 32x64) or 64 (warp tile 32x32; exact-N grids)
// EPI: 0=bias, 1=bias+gelu, 2=bias+residual, 4=exp(acc-aux[row])*64^-.25
// =====================================================================
#define MMA_BF16(d, a, b) \
  asm volatile("mma.sync.aligned.m16n8k16.row.col.f32.bf16.bf16.f32 " \
    "{%0,%1,%2,%3}, {%4,%5,%6,%7}, {%8,%9}, {%0,%1,%2,%3};" \
    : "+f"((d)[0]), "+f"((d)[1]), "+f"((d)[2]), "+f"((d)[3]) \
    : "r"((a)[0]), "r"((a)[1]), "r"((a)[2]), "r"((a)[3]), \
      "r"((b)[0]), "r"((b)[1]))

#define PACK_BF2(w, flo, fhi) \
  asm("cvt.rn.bf16x2.f32 %0, %1, %2;" : "=r"(w) : "f"(fhi), "f"(flo))

__device__ __forceinline__ void split_pair(float x0, float x1,
                                           uint32_t& h, uint32_t& l) {
    PACK_BF2(h, x0, x1);
    float h0 = __uint_as_float(h << 16);
    float h1 = __uint_as_float(h & 0xffff0000u);
    PACK_BF2(l, x0 - h0, x1 - h1);
}

#define B3_ROW 20
#define A_TILE (128*B3_ROW)
template<int BNv> struct SmemSz {
    static constexpr int BT = BNv * B3_ROW;
    static constexpr int BYTES = (4 * A_TILE + 4 * BT) * 4;
};

template<int EPI, int BNv>
__global__ __launch_bounds__(256, 2)
void bf3_gemm(const float* __restrict__ A, const float* __restrict__ Bt,
              const float* __restrict__ bias, const float* __restrict__ res,
              const float* __restrict__ aux, float* __restrict__ C,
              int M, int Nreal, int K, long bRows)
{
    constexpr int NT = BNv / 16;
    constexpr int BT = BNv * B3_ROW;
    extern __shared__ uint32_t smu[];
    uint32_t* Abase = smu;
    uint32_t* Bbase = smu + 4 * A_TILE;

    int tid = threadIdx.x;
    int lane = tid & 31, wid = tid >> 5;
    int wm = (wid & 3) * 32;
    int wn = (wid >> 2) * (BNv / 2);
    int mBase = blockIdx.y * 128, nBase = blockIdx.x * BNv;

    float acc[2][NT][4];
    #pragma unroll
    for (int mt = 0; mt < 2; mt++)
        #pragma unroll
        for (int nt = 0; nt < NT; nt++)
            #pragma unroll
            for (int q = 0; q < 4; q++) acc[mt][nt][q] = 0.f;

    auto ldA = [&](uint32_t* dhi, uint32_t* dlo, int k0) {
        int r = tid >> 1, half = tid & 1;
        long gr = (long)mBase + r;
        float f[16];
        if (gr < M) {
            const float4* src = (const float4*)(A + gr * (long)K + k0 + half * 16);
            #pragma unroll
            for (int u = 0; u < 4; u++) {
                float4 v = src[u];
                f[4*u] = v.x; f[4*u+1] = v.y; f[4*u+2] = v.z; f[4*u+3] = v.w;
            }
        } else {
            #pragma unroll
            for (int u = 0; u < 16; u++) f[u] = 0.f;
        }
        uint32_t hw[8], lw[8];
        #pragma unroll
        for (int p = 0; p < 8; p++) split_pair(f[2*p], f[2*p+1], hw[p], lw[p]);
        uint32_t* ph = dhi + r * B3_ROW + half * 8;
        uint32_t* pl = dlo + r * B3_ROW + half * 8;
        *(uint4*)ph       = make_uint4(hw[0], hw[1], hw[2], hw[3]);
        *(uint4*)(ph + 4) = make_uint4(hw[4], hw[5], hw[6], hw[7]);
        *(uint4*)pl       = make_uint4(lw[0], lw[1], lw[2], lw[3]);
        *(uint4*)(pl + 4) = make_uint4(lw[4], lw[5], lw[6], lw[7]);
    };

    auto ldB = [&](uint32_t* dhi, uint32_t* dlo, int k0) {
        if (BNv == 128) {
            int r = tid >> 1, half = tid & 1;
            long gr = (long)nBase + r;
            float f[16];
            if (gr < bRows) {
                const float4* src = (const float4*)(Bt + gr * (long)K + k0 + half * 16);
                #pragma unroll
                for (int u = 0; u < 4; u++) {
                    float4 v = src[u];
                    f[4*u] = v.x; f[4*u+1] = v.y; f[4*u+2] = v.z; f[4*u+3] = v.w;
                }
            } else {
                #pragma unroll
                for (int u = 0; u < 16; u++) f[u] = 0.f;
            }
            uint32_t hw[8], lw[8];
            #pragma unroll
            for (int p = 0; p < 8; p++) split_pair(f[2*p], f[2*p+1], hw[p], lw[p]);
            uint32_t* ph = dhi + r * B3_ROW + half * 8;
            uint32_t* pl = dlo + r * B3_ROW + half * 8;
            *(uint4*)ph       = make_uint4(hw[0], hw[1], hw[2], hw[3]);
            *(uint4*)(ph + 4) = make_uint4(hw[4], hw[5], hw[6], hw[7]);
            *(uint4*)pl       = make_uint4(lw[0], lw[1], lw[2], lw[3]);
            *(uint4*)(pl + 4) = make_uint4(lw[4], lw[5], lw[6], lw[7]);
        } else {   // BNv == 64: 4 threads per row, 8 floats each
            int r = tid >> 2, q = tid & 3;
            long gr = (long)nBase + r;
            float f[8];
            if (gr < bRows) {
                const float4* src = (const float4*)(Bt + gr * (long)K + k0 + q * 8);
                float4 v0 = src[0], v1 = src[1];
                f[0]=v0.x; f[1]=v0.y; f[2]=v0.z; f[3]=v0.w;
                f[4]=v1.x; f[5]=v1.y; f[6]=v1.z; f[7]=v1.w;
            } else {
                #pragma unroll
                for (int u = 0; u < 8; u++) f[u] = 0.f;
            }
            uint32_t hw[4], lw[4];
            #pragma unroll
            for (int p = 0; p < 4; p++) split_pair(f[2*p], f[2*p+1], hw[p], lw[p]);
            *(uint4*)(dhi + r * B3_ROW + q * 4) = make_uint4(hw[0], hw[1], hw[2], hw[3]);
            *(uint4*)(dlo + r * B3_ROW + q * 4) = make_uint4(lw[0], lw[1], lw[2], lw[3]);
        }
    };

    // EPI 4: per-row sumsq/2 pre-pass (K == 64 for fmap)
    __shared__ float snrm[128];
    if (EPI == 4) {
        int r = tid >> 1, half = tid & 1;
        long gr = (long)mBase + r;
        float ss = 0.f;
        if (gr < M) {
            const float4* src = (const float4*)(A + gr * (long)K + half * 32);
            #pragma unroll
            for (int u = 0; u < 8; u++) {
                float4 vv = src[u];
                ss += vv.x * vv.x + vv.y * vv.y + vv.z * vv.z + vv.w * vv.w;
            }
        }
        ss += __shfl_xor_sync(0xffffffffu, ss, 1);
        if (half == 0) snrm[r] = ss * 0.5f;
    }

    ldA(Abase, Abase + A_TILE, 0);
    ldB(Bbase, Bbase + BT, 0);
    __syncthreads();

    int nSteps = K / 32;
    for (int s = 0; s < nSteps; s++) {
        int buf = s & 1;
        if (s + 1 < nSteps) {
            int nb = buf ^ 1;
            ldA(Abase + nb * 2 * A_TILE, Abase + nb * 2 * A_TILE + A_TILE, (s + 1) * 32);
            ldB(Bbase + nb * 2 * BT,     Bbase + nb * 2 * BT + BT,         (s + 1) * 32);
        }
        const uint32_t* Ah = Abase + buf * 2 * A_TILE;
        const uint32_t* Al = Ah + A_TILE;
        const uint32_t* Bh = Bbase + buf * 2 * BT;
        const uint32_t* Bl = Bh + BT;
        #pragma unroll
        for (int h16 = 0; h16 < 2; h16++) {
            int wb = h16 * 8 + (lane & 3);
            uint32_t ah[2][4], al[2][4];
            #pragma unroll
            for (int mt = 0; mt < 2; mt++) {
                int r0 = (wm + mt * 16 + (lane >> 2)) * B3_ROW + wb;
                ah[mt][0] = Ah[r0];
                ah[mt][1] = Ah[r0 + 8 * B3_ROW];
                ah[mt][2] = Ah[r0 + 4];
                ah[mt][3] = Ah[r0 + 8 * B3_ROW + 4];
                al[mt][0] = Al[r0];
                al[mt][1] = Al[r0 + 8 * B3_ROW];
                al[mt][2] = Al[r0 + 4];
                al[mt][3] = Al[r0 + 8 * B3_ROW + 4];
            }
            #pragma unroll
            for (int nt = 0; nt < NT; nt++) {
                int rb = (wn + nt * 8 + (lane >> 2)) * B3_ROW + wb;
                uint32_t bh[2] = { Bh[rb], Bh[rb + 4] };
                uint32_t bl[2] = { Bl[rb], Bl[rb + 4] };
                #pragma unroll
                for (int mt = 0; mt < 2; mt++) {
                    MMA_BF16(acc[mt][nt], ah[mt], bh);
                    MMA_BF16(acc[mt][nt], ah[mt], bl);
                    MMA_BF16(acc[mt][nt], al[mt], bh);
                }
            }
        }
        __syncthreads();
    }

    // ---- epilogue ----
    #pragma unroll
    for (int mt = 0; mt < 2; mt++) {
        int r0loc = wm + mt * 16 + (lane >> 2);
        #pragma unroll
        for (int e = 0; e < 2; e++) {
            int rowLoc = r0loc + e * 8;
            int row = mBase + rowLoc;
            if (row >= M) continue;
            float auxv = (EPI == 4) ? snrm[rowLoc] : 0.f;
            float* Cp = C + (long)row * Nreal;
            const float* Rp = (EPI == 2) ? res + (long)row * Nreal : nullptr;
            #pragma unroll
            for (int nt = 0; nt < NT; nt++) {
                int c0 = nBase + wn + nt * 8 + 2 * (lane & 3);
                #pragma unroll
                for (int q = 0; q < 2; q++) {
                    int col = c0 + q;
                    if (col >= Nreal) continue;
                    float v = acc[mt][nt][e * 2 + q];
                    if (EPI == 4) {
                        v = __expf(v - auxv) * 0.35355339059327373f;
                    } else {
                        v += bias[col];
                        if (EPI == 1) v = 0.5f * v * (1.0f + erff(v * 0.70710678118654752f));
                        if (EPI == 2) v += Rp[col];
                    }
                    Cp[col] = v;
                }
            }
        }
    }
}

// ---------------- weight transpose+pad ----------------
__global__ void transp_k(const float* __restrict__ in, float* __restrict__ out,
                         int K, int N, int Npad)
{
    int z = blockIdx.y;
    long idx = (long)blockIdx.x * 256 + threadIdx.x;
    if (idx >= (long)Npad * K) return;
    int n = (int)(idx / K), k = (int)(idx % K);
    out[(long)z * Npad * K + idx] =
        (n < N) ? in[(long)z * K * N + (long)k * N + n] : 0.f;
}

// ---------------- SIMT FFMA2 GEMM (batched kv/ao) ----------------
#define FMA2(acc, a, b) asm("fma.rn.f32x2 %0, %1, %2, %0;" : "+l"(acc) : "l"(a), "l"(b))
#define PACK2(dst, s)   asm("mov.b64 %0, {%1, %1};" : "=l"(dst) : "f"(s))
#define BKq 16

template<int EPI, bool TA, int BMv, int BNv>
__global__ __launch_bounds__((BMv/8)*(BNv/8), 3)
void gemm3_k(const float* __restrict__ A, const float* __restrict__ Bm,
             const float* __restrict__ aux, float* __restrict__ C,
             int M, int N, int K, long sA, long sB, long sC)
{
    constexpr int THREADS = (BMv/8)*(BNv/8);
    constexpr int CT = BNv/8;
    __shared__ __align__(16) float As[2][BKq][BMv + 4];
    __shared__ __align__(16) float Bs[2][BKq][BNv + 4];

    int z = blockIdx.z;
    const float* Ab = A + (long)z * sA;
    const float* Bb = Bm + (long)z * sB;
    int mBase = blockIdx.y * BMv;
    int nBase = blockIdx.x * BNv;
    int tid = threadIdx.x;
    int rt = tid / CT, ct = tid % CT;

    unsigned long long acc[8][4];
    #pragma unroll
    for (int i = 0; i < 8; i++)
        #pragma unroll
        for (int j = 0; j < 4; j++) acc[i][j] = 0ULL;

    auto loadTile = [&](int buf, int k0) {
        if (TA) {
            constexpr int F = 4 * BMv / THREADS;
            #pragma unroll
            for (int f = 0; f < F; f++) {
                int l = tid + f * THREADS;
                int kk = l / (BMv / 4);
                int m4 = (l % (BMv / 4)) * 4;
                int gk = k0 + kk;
                float4 v = make_float4(0.f, 0.f, 0.f, 0.f);
                if (gk < K) {
                    float t[4];
                    #pragma unroll
                    for (int u = 0; u < 4; u++)
                        t[u] = (mBase + m4 + u < M) ? Ab[(long)gk * M + mBase + m4 + u] : 0.f;
                    v = make_float4(t[0], t[1], t[2], t[3]);
                }
                *(float4*)&As[buf][kk][m4] = v;
            }
        } else {
            constexpr int F = 4 * BMv / THREADS;
            #pragma unroll
            for (int f = 0; f < F; f++) {
                int l = tid + f * THREADS;
                int m = l >> 2, k4 = (l & 3) * 4;
                int gm = mBase + m;
                float4 v = make_float4(0.f, 0.f, 0.f, 0.f);
                if (gm < M) {
                    if (k0 + k4 + 3 < K) {
                        v = *(const float4*)(Ab + (long)gm * K + k0 + k4);
                    } else {
                        float t[4];
                        #pragma unroll
                        for (int u = 0; u < 4; u++)
                            t[u] = (k0 + k4 + u < K) ? Ab[(long)gm * K + k0 + k4 + u] : 0.f;
                        v = make_float4(t[0], t[1], t[2], t[3]);
                    }
                }
                As[buf][k4 + 0][m] = v.x;
                As[buf][k4 + 1][m] = v.y;
                As[buf][k4 + 2][m] = v.z;
                As[buf][k4 + 3][m] = v.w;
            }
        }
        {
            constexpr int F = 4 * BNv / THREADS;
            #pragma unroll
            for (int f = 0; f < F; f++) {
                int l = tid + f * THREADS;
                int kk = l / (BNv / 4);
                int n4 = (l % (BNv / 4)) * 4;
                int gk = k0 + kk;
                float4 v = make_float4(0.f, 0.f, 0.f, 0.f);
                if (gk < K) {
                    if (nBase + n4 + 3 < N) {
                        v = *(const float4*)(Bb + (long)gk * N + nBase + n4);
                    } else {
                        float t[4];
                        #pragma unroll
                        for (int u = 0; u < 4; u++)
                            t[u] = (nBase + n4 + u < N) ? Bb[(long)gk * N + nBase + n4 + u] : 0.f;
                        v = make_float4(t[0], t[1], t[2], t[3]);
                    }
                }
                *(float4*)&Bs[buf][kk][n4] = v;
            }
        }
    };

    int buf = 0;
    loadTile(0, 0);
    __syncthreads();
    for (int k0 = 0; k0 < K; k0 += BKq) {
        if (k0 + BKq < K) loadTile(buf ^ 1, k0 + BKq);
        #pragma unroll
        for (int kk = 0; kk < BKq; kk++) {
            float4 a0 = *(const float4*)&As[buf][kk][rt * 8];
            float4 a1 = *(const float4*)&As[buf][kk][rt * 8 + 4];
            ulonglong2 b0 = *(const ulonglong2*)&Bs[buf][kk][ct * 8];
            ulonglong2 b1 = *(const ulonglong2*)&Bs[buf][kk][ct * 8 + 4];
            unsigned long long bp[4] = {b0.x, b0.y, b1.x, b1.y};
            float av[8] = {a0.x, a0.y, a0.z, a0.w, a1.x, a1.y, a1.z, a1.w};
            unsigned long long ap[8];
            #pragma unroll
            for (int i = 0; i < 8; i++) PACK2(ap[i], av[i]);
            #pragma unroll
            for (int i = 0; i < 8; i++)
                #pragma unroll
                for (int j = 0; j < 4; j++)
                    FMA2(acc[i][j], ap[i], bp[j]);
        }
        __syncthreads();
        buf ^= 1;
    }

    union F2 { unsigned long long u; float2 f; };
    if (EPI == 3) {
        int bb = z / 3, hh = z % 3;
        float* Cp = C + (long)bb * NTOK * EMBED + hh * HDIM;
        #pragma unroll
        for (int i = 0; i < 8; i++) {
            int row = mBase + rt * 8 + i;
            if (row >= M) continue;
            float dvv = aux[(long)z * NTOK + row];
            #pragma unroll
            for (int j = 0; j < 4; j++) {
                int cb = nBase + ct * 8 + 2 * j;
                if (cb >= N) continue;
                F2 t; t.u = acc[i][j];
                t.f.x *= dvv; t.f.y *= dvv;
                *(float2*)&Cp[(long)row * EMBED + cb] = t.f;
            }
        }
    } else {
        float* Cp = C + (long)z * sC;
        #pragma unroll
        for (int i = 0; i < 8; i++) {
            int row = mBase + rt * 8 + i;
            if (row >= M) continue;
            #pragma unroll
            for (int j = 0; j < 4; j++) {
                int cb = nBase + ct * 8 + 2 * j;
                if (cb >= N) continue;
                F2 t; t.u = acc[i][j];
                *(float2*)&Cp[(long)row * N + cb] = t.f;
            }
        }
    }
}

// ---------------- LayerNorm (warp per row) ----------------
__global__ __launch_bounds__(256)
void ln_k(const float* __restrict__ in, long rowStride,
          const float* __restrict__ w, const float* __restrict__ b,
          float* __restrict__ out, int nRows)
{
    int warp = (blockIdx.x * 256 + threadIdx.x) >> 5;
    int lane = threadIdx.x & 31;
    if (warp >= nRows) return;
    const float* ip = in + (long)warp * rowStride;
    float2 v[3];
    #pragma unroll
    for (int j = 0; j < 3; j++)
        v[j] = *(const float2*)(ip + j * 64 + lane * 2);
    float s = v[0].x + v[0].y + v[1].x + v[1].y + v[2].x + v[2].y;
    float mu = warpSum(s) * (1.f / EMBED);
    float q = 0.f;
    #pragma unroll
    for (int j = 0; j < 3; j++) {
        v[j].x -= mu; v[j].y -= mu;
        q += v[j].x * v[j].x + v[j].y * v[j].y;
    }
    float rstd = rsqrtf(warpSum(q) * (1.f / EMBED) + 1e-5f);
    float* op = out + (long)warp * EMBED;
    #pragma unroll
    for (int j = 0; j < 3; j++) {
        int c = j * 64 + lane * 2;
        float2 wv = *(const float2*)(w + c);
        float2 bv = *(const float2*)(b + c);
        float2 o = make_float2(v[j].x * rstd * wv.x + bv.x,
                               v[j].y * rstd * wv.y + bv.y);
        *(float2*)(op + c) = o;
    }
}

__global__ __launch_bounds__(256)
void lnpos_k(const float* __restrict__ tok, const float* __restrict__ w,
             const float* __restrict__ b, const float* __restrict__ pos,
             float* __restrict__ h)
{
    int warp = (blockIdx.x * 256 + threadIdx.x) >> 5;
    int lane = threadIdx.x & 31;
    if (warp >= NPATCH * BATCH) return;
    int bb = warp / NPATCH, p = warp % NPATCH;
    const float* ip = tok + (long)warp * EMBED;
    float2 v[3];
    #pragma unroll
    for (int j = 0; j < 3; j++)
        v[j] = *(const float2*)(ip + j * 64 + lane * 2);
    float s = v[0].x + v[0].y + v[1].x + v[1].y + v[2].x + v[2].y;
    float mu = warpSum(s) * (1.f / EMBED);
    float q = 0.f;
    #pragma unroll
    for (int j = 0; j < 3; j++) {
        v[j].x -= mu; v[j].y -= mu;
        q += v[j].x * v[j].x + v[j].y * v[j].y;
    }
    float rstd = rsqrtf(warpSum(q) * (1.f / EMBED) + 1e-5f);
    float* op = h + ((long)bb * NTOK + 1 + p) * EMBED;
    const float* pp = pos + (1 + p) * EMBED;
    #pragma unroll
    for (int j = 0; j < 3; j++) {
        int c = j * 64 + lane * 2;
        float2 wv = *(const float2*)(w + c);
        float2 bv = *(const float2*)(b + c);
        float2 pv = *(const float2*)(pp + c);
        float2 o = make_float2(v[j].x * rstd * wv.x + bv.x + pv.x,
                               v[j].y * rstd * wv.y + bv.y + pv.y);
        *(float2*)(op + c) = o;
    }
}

__global__ void im2col_k(const float* __restrict__ x, float* __restrict__ px)
{
    long idx = (long)blockIdx.x * 256 + threadIdx.x;
    if (idx >= (long)NPATCH * BATCH * 768) return;
    int t = (int)(idx % 768);
    long rp = idx / 768;
    int b = (int)(rp / NPATCH), p = (int)(rp % NPATCH);
    int c = t >> 8, rem = t & 255, r = rem >> 4, col = rem & 15;
    int gy = p / 14, gx = p % 14;
    px[idx] = x[(((long)b * 3 + c) * 224 + gy * 16 + r) * 224 + gx * 16 + col];
}

__global__ void cls_k(const float* __restrict__ cls, const float* __restrict__ pos,
                      float* __restrict__ h)
{
    int b = blockIdx.x; int e = threadIdx.x;
    h[(long)b * NTOK * EMBED + e] = cls[e] + pos[e];
}

// ---------------- split: warp per (row, head) ----------------
__global__ __launch_bounds__(192)
void split_k(const float* __restrict__ qkv, float* __restrict__ qk,
             float* __restrict__ v, float* __restrict__ nrm)
{
    int wid = threadIdx.x >> 5;
    int lane = threadIdx.x & 31;
    int row = blockIdx.x * 2 + wid / 3;
    if (row >= ROWS) return;
    int hh = wid % 3;
    int b = row / NTOK, n = row % NTOK;
    const float* base = qkv + (long)row * 576 + hh * 64 + lane * 2;
    float2 qv = *(const float2*)base;
    float2 kv = *(const float2*)(base + 192);
    float2 vv = *(const float2*)(base + 384);
    long o = (((long)b * 3 + hh) * NTOK + n) * 64 + lane * 2;
    *(float2*)(qk + o) = qv;
    *(float2*)(qk + (long)BHN * HDIM + o) = kv;
    *(float2*)(v + o) = vv;
    float sq = warpSum(qv.x * qv.x + qv.y * qv.y);
    float sk = warpSum(kv.x * kv.x + kv.y * kv.y);
    if (lane == 0) {
        long r = ((long)b * 3 + hh) * NTOK + n;
        nrm[r]       = sq * 0.5f;
        nrm[BHN + r] = sk * 0.5f;
    }
}

// ---------------- ksum 2-pass ----------------
__global__ void ksum1_k(const float* __restrict__ pk, float* __restrict__ part)
{
    int z = blockIdx.x, chunk = blockIdx.y, f = threadIdx.x;
    int n0 = chunk * 29;
    int n1 = n0 + 29; if (n1 > NTOK) n1 = NTOK;
    float s = 0.f;
    for (int n = n0; n < n1; n++) s += pk[((long)z * NTOK + n) * FEAT + f];
    part[((long)chunk * BATCH * HEADS + z) * FEAT + f] = s;
}
__global__ void ksum2_k(const float* __restrict__ part, float* __restrict__ ks)
{
    int z = blockIdx.x, f = threadIdx.x;
    float s = 0.f;
    #pragma unroll
    for (int c = 0; c < 7; c++)
        s += part[((long)c * BATCH * HEADS + z) * FEAT + f];
    ks[(long)z * FEAT + f] = s;
}

// ---------------- D_inv ----------------
__global__ __launch_bounds__(256)
void dinv_k(const float* __restrict__ pq, const float* __restrict__ ks,
            float* __restrict__ dv)
{
    __shared__ float s[FEAT];
    int z = blockIdx.x;
    int tid = threadIdx.x;
    s[tid] = ks[(long)z * FEAT + tid];
    __syncthreads();
    int w = tid >> 5, l = tid & 31;
    int n = blockIdx.y * 8 + w;
    if (n < NTOK) {
        const float* p = pq + ((long)z * NTOK + n) * FEAT;
        float acc = 0.f;
        #pragma unroll
        for (int f = 0; f < FEAT / 32; f++) acc += p[l + f * 32] * s[l + f * 32];
        acc = warpSum(acc);
        if (l == 0) dv[(long)z * NTOK + n] = 1.f / acc;
    }
}

// ---------------- pool 2-pass ----------------
__global__ void pool1_k(const float* __restrict__ h, float* __restrict__ part)
{
    int b = blockIdx.x, chunk = blockIdx.y, e = threadIdx.x;
    int n0 = chunk * 8;
    int n1 = n0 + 8; if (n1 > NTOK) n1 = NTOK;
    float s = 0.f;
    for (int n = n0; n < n1; n++) s += h[((long)b * NTOK + n) * EMBED + e];
    part[((long)chunk * BATCH + b) * EMBED + e] = s;
}
__global__ void pool2_k(const float* __restrict__ part, float* __restrict__ pool)
{
    int b = blockIdx.x, e = threadIdx.x;
    float s = 0.f;
    #pragma unroll
    for (int c = 0; c < 25; c++)
        s += part[((long)c * BATCH + b) * EMBED + e];
    pool[(long)b * EMBED + e] = s * (1.f / 197.f);
}

// ---------------- host launch ----------------
extern "C" void kernel_launch(void* const* d_in, const int* in_sizes, int n_in,
                              void* d_out, int out_size)
{
    const float* x            = (const float*)d_in[0];
    const float* patch_w      = (const float*)d_in[1];
    const float* patch_b      = (const float*)d_in[2];
    const float* pe_norm_w    = (const float*)d_in[3];
    const float* pe_norm_b    = (const float*)d_in[4];
    const float* cls_token    = (const float*)d_in[5];
    const float* pos_embed    = (const float*)d_in[6];
    const float* norm1_w      = (const float*)d_in[7];
    const float* norm1_b      = (const float*)d_in[8];
    const float* qkv_w        = (const float*)d_in[9];
    const float* qkv_b        = (const float*)d_in[10];
    const float* proj_mat     = (const float*)d_in[11];
    const float* attn_proj_w  = (const float*)d_in[12];
    const float* attn_proj_b  = (const float*)d_in[13];
    const float* norm2_w      = (const float*)d_in[14];
    const float* norm2_b      = (const float*)d_in[15];
    const float* fc1_w        = (const float*)d_in[16];
    const float* fc1_b        = (const float*)d_in[17];
    const float* fc2_w        = (const float*)d_in[18];
    const float* fc2_b        = (const float*)d_in[19];
    const float* exit_w       = (const float*)d_in[20];
    const float* exit_b       = (const float*)d_in[21];
    const float* final_norm_w = (const float*)d_in[22];
    const float* final_norm_b = (const float*)d_in[23];
    const float* head_w       = (const float*)d_in[24];
    const float* head_b       = (const float*)d_in[25];
    float* out = (float*)d_out;

    float *h, *xln, *qkv, *qk, *v, *nrm, *pqk, *ks, *kspart, *dv, *kv, *ao, *mlp;
    float *pool, *poolpart, *cls;
    float *wqkvT, *wapT, *wfc1T, *wfc2T, *wexT, *whdT;
    cudaGetSymbolAddress((void**)&h,    g_h);
    cudaGetSymbolAddress((void**)&xln,  g_xln);
    cudaGetSymbolAddress((void**)&qkv,  g_qkv);
    cudaGetSymbolAddress((void**)&qk,   g_qk);
    cudaGetSymbolAddress((void**)&v,    g_v);
    cudaGetSymbolAddress((void**)&nrm,  g_nrm);
    cudaGetSymbolAddress((void**)&pqk,  g_pqk);
    cudaGetSymbolAddress((void**)&ks,   g_ks);
    cudaGetSymbolAddress((void**)&kspart, g_kspart);
    cudaGetSymbolAddress((void**)&dv,   g_dv);
    cudaGetSymbolAddress((void**)&kv,   g_kv);
    cudaGetSymbolAddress((void**)&ao,   g_ao);
    cudaGetSymbolAddress((void**)&mlp,  g_mlp);
    cudaGetSymbolAddress((void**)&pool, g_pool);
    cudaGetSymbolAddress((void**)&poolpart, g_poolpart);
    cudaGetSymbolAddress((void**)&cls,  g_cls);
    cudaGetSymbolAddress((void**)&wqkvT, g_wqkvT);
    cudaGetSymbolAddress((void**)&wapT,  g_wapT);
    cudaGetSymbolAddress((void**)&wfc1T, g_wfc1T);
    cudaGetSymbolAddress((void**)&wfc2T, g_wfc2T);
    cudaGetSymbolAddress((void**)&wexT,  g_wexT);
    cudaGetSymbolAddress((void**)&whdT,  g_whdT);

    constexpr int SM128 = SmemSz<128>::BYTES;
    constexpr int SM64  = SmemSz<64>::BYTES;
    cudaFuncSetAttribute(bf3_gemm<0,128>, cudaFuncAttributeMaxDynamicSharedMemorySize, SM128);
    cudaFuncSetAttribute(bf3_gemm<1,128>, cudaFuncAttributeMaxDynamicSharedMemorySize, SM128);
    cudaFuncSetAttribute(bf3_gemm<4,128>, cudaFuncAttributeMaxDynamicSharedMemorySize, SM128);
    cudaFuncSetAttribute(bf3_gemm<0,64>,  cudaFuncAttributeMaxDynamicSharedMemorySize, SM64);
    cudaFuncSetAttribute(bf3_gemm<2,64>,  cudaFuncAttributeMaxDynamicSharedMemorySize, SM64);

    const float* pk = pqk + (long)BHN * FEAT;

    // ---- weight transposes (into [N][K] K-major; patch_w/proj_mat already are)
    transp_k<<<dim3((576*192 + 255)/256, DEPTH), 256>>>(qkv_w, wqkvT, 192, 576, 576);
    transp_k<<<dim3((192*192 + 255)/256, DEPTH), 256>>>(attn_proj_w, wapT, 192, 192, 192);
    transp_k<<<dim3((768*192 + 255)/256, DEPTH), 256>>>(fc1_w, wfc1T, 192, 768, 768);
    transp_k<<<dim3((192*768 + 255)/256, DEPTH), 256>>>(fc2_w, wfc2T, 768, 192, 192);
    transp_k<<<dim3((1024*192 + 255)/256, 3), 256>>>(exit_w, wexT, 192, 1000, 1024);
    transp_k<<<dim3((1024*192 + 255)/256, 1), 256>>>(head_w, whdT, 192, 1000, 1024);

    // ---- patch embed: im2col -> bf3 GEMM (BN64, exact; patch_w direct) ----
    cls_k<<<BATCH, EMBED>>>(cls_token, pos_embed, h);
    im2col_k<<<(int)(((long)NPATCH * BATCH * 768 + 255) / 256), 256>>>(x, mlp);
    bf3_gemm<0,64><<<dim3(3, 98), 256, SM64>>>(
        mlp, patch_w, patch_b, nullptr, nullptr, ao, NPATCH * BATCH, EMBED, 768, 192);
    lnpos_k<<<(NPATCH * BATCH * 32 + 255) / 256, 256>>>(
        ao, pe_norm_w, pe_norm_b, pos_embed, h);

    int lnBlocks = (ROWS * 32 + 255) / 256;
    for (int i = 0; i < DEPTH; i++) {
        ln_k<<<lnBlocks, 256>>>(h, EMBED, norm1_w + i * EMBED, norm1_b + i * EMBED,
                                xln, ROWS);
        // qkv (BN64; N=576 exact, no padding)
        bf3_gemm<0,64><<<dim3(9, 99), 256, SM64>>>(
            xln, wqkvT + (long)i * 576 * 192, qkv_b + i * 3 * EMBED,
            nullptr, nullptr, qkv, ROWS, 3 * EMBED, EMBED, 576);
        split_k<<<(ROWS + 1) / 2, 192>>>(qkv, qk, v, nrm);
        // feature maps (BN128; N=256 exact); proj_mat is [N][K] already
        bf3_gemm<4,128><<<dim3(2, 591), 256, SM128>>>(
            qk, proj_mat + (long)i * FEAT * HDIM, nullptr, nullptr, nrm, pqk,
            2 * BHN, FEAT, HDIM, FEAT);
        ksum1_k<<<dim3(BATCH * HEADS, 7), FEAT>>>(pk, kspart);
        ksum2_k<<<BATCH * HEADS, FEAT>>>(kspart, ks);
        dinv_k<<<dim3(BATCH * HEADS, 25), 256>>>(pqk, ks, dv);
        // kv = pk^T @ v  (SIMT)
        gemm3_k<0,true,128,64><<<dim3(1, 2, BATCH * HEADS), 128>>>(
            pk, v, nullptr, kv,
            FEAT, HDIM, NTOK, (long)NTOK * FEAT, (long)NTOK * HDIM, (long)FEAT * HDIM);
        // ao = (pq @ kv) * D_inv  (SIMT, scatter)
        gemm3_k<3,false,128,64><<<dim3(1, 2, BATCH * HEADS), 128>>>(
            pqk, kv, dv, ao,
            NTOK, HDIM, FEAT, (long)NTOK * FEAT, (long)FEAT * HDIM, 0);
        // attn proj + residual (BN64, exact N=192)
        bf3_gemm<2,64><<<dim3(3, 99), 256, SM64>>>(
            ao, wapT + (long)i * 192 * 192, attn_proj_b + i * EMBED,
            h, nullptr, h, ROWS, EMBED, EMBED, 192);
        ln_k<<<lnBlocks, 256>>>(h, EMBED, norm2_w + i * EMBED, norm2_b + i * EMBED,
                                xln, ROWS);
        // MLP: fc1 BN128 (N=768 exact), fc2 BN64 (N=192 exact)
        bf3_gemm<1,128><<<dim3(6, 99), 256, SM128>>>(
            xln, wfc1T + (long)i * 768 * 192, fc1_b + i * MLPD,
            nullptr, nullptr, mlp, ROWS, MLPD, EMBED, 768);
        bf3_gemm<2,64><<<dim3(3, 99), 256, SM64>>>(
            mlp, wfc2T + (long)i * 192 * 768, fc2_b + i * EMBED,
            h, nullptr, h, ROWS, EMBED, MLPD, 192);
        if (i == 3 || i == 7 || i == 11) {
            int e = (i == 3) ? 0 : (i == 7) ? 1 : 2;
            pool1_k<<<dim3(BATCH, 25), EMBED>>>(h, poolpart);
            pool2_k<<<BATCH, EMBED>>>(poolpart, pool);
            bf3_gemm<0,128><<<dim3(8, 1), 256, SM128>>>(
                pool, wexT + (long)e * 1024 * 192, exit_b + e * NCLS,
                nullptr, nullptr, out + (long)(1 + e) * BATCH * NCLS,
                BATCH, NCLS, EMBED, 1024);
        }
    }

    ln_k<<<(BATCH * 32 + 255) / 256, 256>>>(
        h, (long)NTOK * EMBED, final_norm_w, final_norm_b, cls, BATCH);
    bf3_gemm<0,128><<<dim3(8, 1), 256, SM128>>>(
        cls, whdT, head_b, nullptr, nullptr, out, BATCH, NCLS, EMBED, 1024);
}

// round 15
// speedup vs baseline: 1.1739x; 1.1051x over previous
#include <cuda_runtime.h>
#include <cuda_bf16.h>
#include <math.h>
#include <cstdint>

// ---------------- problem constants ----------------
#define BATCH 64
#define NTOK 197
#define NPATCH 196
#define EMBED 192
#define HEADS 3
#define HDIM 64
#define FEAT 256
#define MLPD 768
#define NCLS 1000
#define DEPTH 12
#define ROWS (BATCH*NTOK)          // 12608
#define BHN  (BATCH*HEADS*NTOK)    // 37824
#define ZB   (BATCH*HEADS)         // 192

// ---------------- scratch (device globals) ----------------
__device__ float g_h   [ROWS*EMBED];
__device__ float g_xln [ROWS*EMBED];
__device__ float g_qkv [ROWS*3*EMBED];
__device__ float g_qk  [2L*BHN*HDIM];
__device__ float g_v   [BHN*HDIM];
__device__ float g_nrm [2L*BHN];
__device__ float g_pqk [2L*BHN*FEAT];
__device__ float g_ks  [ZB*FEAT];
__device__ float g_kspart [7*ZB*FEAT];
__device__ float g_dv  [ZB*NTOK];
__device__ float g_kvT [ZB*HDIM*FEAT];    // per z: [64][256]  (B operand for ao)
__device__ float g_ao  [ROWS*EMBED];
__device__ float g_mlp [ROWS*MLPD];
__device__ float g_pool[BATCH*EMBED];
__device__ float g_poolpart[25*BATCH*EMBED];
__device__ float g_cls [BATCH*EMBED];
// transposed weights [N][K] (K-major)
__device__ float g_wqkvT [DEPTH*576*192];
__device__ float g_wapT  [DEPTH*192*192];
__device__ float g_wfc1T [DEPTH*768*192];
__device__ float g_wfc2T [DEPTH*192*768];
__device__ float g_wexT  [3*1024*192];
__device__ float g_whdT  [1024*192];

__device__ __forceinline__ float warpSum(float v) {
    #pragma unroll
    for (int o = 16; o > 0; o >>= 1) v += __shfl_xor_sync(0xffffffffu, v, o);
    return v;
}

// =====================================================================
// bf16x3 mma GEMM: C[M,Nreal] = A[M,K] @ Bt^T  (optional batch over z)
// Bt stored [n][k] row-major.
// EPI: 0=bias, 1=bias+gelu, 2=bias+residual,
//      3=dinv-scale + head scatter (batched attention out),
//      4=exp(acc - rowSumSq(A)/2)*64^-0.25
// =====================================================================
#define MMA_BF16(d, a, b) \
  asm volatile("mma.sync.aligned.m16n8k16.row.col.f32.bf16.bf16.f32 " \
    "{%0,%1,%2,%3}, {%4,%5,%6,%7}, {%8,%9}, {%0,%1,%2,%3};" \
    : "+f"((d)[0]), "+f"((d)[1]), "+f"((d)[2]), "+f"((d)[3]) \
    : "r"((a)[0]), "r"((a)[1]), "r"((a)[2]), "r"((a)[3]), \
      "r"((b)[0]), "r"((b)[1]))

#define PACK_BF2(w, flo, fhi) \
  asm("cvt.rn.bf16x2.f32 %0, %1, %2;" : "=r"(w) : "f"(fhi), "f"(flo))

__device__ __forceinline__ void split_pair(float x0, float x1,
                                           uint32_t& h, uint32_t& l) {
    PACK_BF2(h, x0, x1);
    float h0 = __uint_as_float(h << 16);
    float h1 = __uint_as_float(h & 0xffff0000u);
    PACK_BF2(l, x0 - h0, x1 - h1);
}

#define B3_ROW 20
#define A_TILE (128*B3_ROW)
template<int BNv> struct SmemSz {
    static constexpr int BT = BNv * B3_ROW;
    static constexpr int BYTES = (4 * A_TILE + 4 * BT) * 4;
};

template<int EPI, int BNv>
__global__ __launch_bounds__(256, 2)
void bf3_gemm(const float* __restrict__ A, const float* __restrict__ Bt,
              const float* __restrict__ bias, const float* __restrict__ res,
              const float* __restrict__ aux, float* __restrict__ C,
              int M, int Nreal, int K, long bRows, long sA, long sBt)
{
    constexpr int NT = BNv / 16;
    constexpr int BT = BNv * B3_ROW;
    extern __shared__ uint32_t smu[];
    uint32_t* Abase = smu;
    uint32_t* Bbase = smu + 4 * A_TILE;

    int z = blockIdx.z;
    const float* Ab  = A  + (long)z * sA;
    const float* Btb = Bt + (long)z * sBt;

    int tid = threadIdx.x;
    int lane = tid & 31, wid = tid >> 5;
    int wm = (wid & 3) * 32;
    int wn = (wid >> 2) * (BNv / 2);
    int mBase = blockIdx.y * 128, nBase = blockIdx.x * BNv;

    float acc[2][NT][4];
    #pragma unroll
    for (int mt = 0; mt < 2; mt++)
        #pragma unroll
        for (int nt = 0; nt < NT; nt++)
            #pragma unroll
            for (int q = 0; q < 4; q++) acc[mt][nt][q] = 0.f;

    auto ldA = [&](uint32_t* dhi, uint32_t* dlo, int k0) {
        int r = tid >> 1, half = tid & 1;
        long gr = (long)mBase + r;
        float f[16];
        if (gr < M) {
            const float4* src = (const float4*)(Ab + gr * (long)K + k0 + half * 16);
            #pragma unroll
            for (int u = 0; u < 4; u++) {
                float4 v = src[u];
                f[4*u] = v.x; f[4*u+1] = v.y; f[4*u+2] = v.z; f[4*u+3] = v.w;
            }
        } else {
            #pragma unroll
            for (int u = 0; u < 16; u++) f[u] = 0.f;
        }
        uint32_t hw[8], lw[8];
        #pragma unroll
        for (int p = 0; p < 8; p++) split_pair(f[2*p], f[2*p+1], hw[p], lw[p]);
        uint32_t* ph = dhi + r * B3_ROW + half * 8;
        uint32_t* pl = dlo + r * B3_ROW + half * 8;
        *(uint4*)ph       = make_uint4(hw[0], hw[1], hw[2], hw[3]);
        *(uint4*)(ph + 4) = make_uint4(hw[4], hw[5], hw[6], hw[7]);
        *(uint4*)pl       = make_uint4(lw[0], lw[1], lw[2], lw[3]);
        *(uint4*)(pl + 4) = make_uint4(lw[4], lw[5], lw[6], lw[7]);
    };

    auto ldB = [&](uint32_t* dhi, uint32_t* dlo, int k0) {
        if (BNv == 128) {
            int r = tid >> 1, half = tid & 1;
            long gr = (long)nBase + r;
            float f[16];
            if (gr < bRows) {
                const float4* src = (const float4*)(Btb + gr * (long)K + k0 + half * 16);
                #pragma unroll
                for (int u = 0; u < 4; u++) {
                    float4 v = src[u];
                    f[4*u] = v.x; f[4*u+1] = v.y; f[4*u+2] = v.z; f[4*u+3] = v.w;
                }
            } else {
                #pragma unroll
                for (int u = 0; u < 16; u++) f[u] = 0.f;
            }
            uint32_t hw[8], lw[8];
            #pragma unroll
            for (int p = 0; p < 8; p++) split_pair(f[2*p], f[2*p+1], hw[p], lw[p]);
            uint32_t* ph = dhi + r * B3_ROW + half * 8;
            uint32_t* pl = dlo + r * B3_ROW + half * 8;
            *(uint4*)ph       = make_uint4(hw[0], hw[1], hw[2], hw[3]);
            *(uint4*)(ph + 4) = make_uint4(hw[4], hw[5], hw[6], hw[7]);
            *(uint4*)pl       = make_uint4(lw[0], lw[1], lw[2], lw[3]);
            *(uint4*)(pl + 4) = make_uint4(lw[4], lw[5], lw[6], lw[7]);
        } else {   // BNv == 64: 4 threads per row, 8 floats each
            int r = tid >> 2, q = tid & 3;
            long gr = (long)nBase + r;
            float f[8];
            if (gr < bRows) {
                const float4* src = (const float4*)(Btb + gr * (long)K + k0 + q * 8);
                float4 v0 = src[0], v1 = src[1];
                f[0]=v0.x; f[1]=v0.y; f[2]=v0.z; f[3]=v0.w;
                f[4]=v1.x; f[5]=v1.y; f[6]=v1.z; f[7]=v1.w;
            } else {
                #pragma unroll
                for (int u = 0; u < 8; u++) f[u] = 0.f;
            }
            uint32_t hw[4], lw[4];
            #pragma unroll
            for (int p = 0; p < 4; p++) split_pair(f[2*p], f[2*p+1], hw[p], lw[p]);
            *(uint4*)(dhi + r * B3_ROW + q * 4) = make_uint4(hw[0], hw[1], hw[2], hw[3]);
            *(uint4*)(dlo + r * B3_ROW + q * 4) = make_uint4(lw[0], lw[1], lw[2], lw[3]);
        }
    };

    __shared__ float snrm[128];
    if (EPI == 4) {   // per-row sumsq/2 (K == 64 for fmap)
        int r = tid >> 1, half = tid & 1;
        long gr = (long)mBase + r;
        float ss = 0.f;
        if (gr < M) {
            const float4* src = (const float4*)(Ab + gr * (long)K + half * 32);
            #pragma unroll
            for (int u = 0; u < 8; u++) {
                float4 vv = src[u];
                ss += vv.x * vv.x + vv.y * vv.y + vv.z * vv.z + vv.w * vv.w;
            }
        }
        ss += __shfl_xor_sync(0xffffffffu, ss, 1);
        if (half == 0) snrm[r] = ss * 0.5f;
    }

    ldA(Abase, Abase + A_TILE, 0);
    ldB(Bbase, Bbase + BT, 0);
    __syncthreads();

    int nSteps = K / 32;
    for (int s = 0; s < nSteps; s++) {
        int buf = s & 1;
        if (s + 1 < nSteps) {
            int nb = buf ^ 1;
            ldA(Abase + nb * 2 * A_TILE, Abase + nb * 2 * A_TILE + A_TILE, (s + 1) * 32);
            ldB(Bbase + nb * 2 * BT,     Bbase + nb * 2 * BT + BT,         (s + 1) * 32);
        }
        const uint32_t* Ah = Abase + buf * 2 * A_TILE;
        const uint32_t* Al = Ah + A_TILE;
        const uint32_t* Bh = Bbase + buf * 2 * BT;
        const uint32_t* Bl = Bh + BT;
        #pragma unroll
        for (int h16 = 0; h16 < 2; h16++) {
            int wb = h16 * 8 + (lane & 3);
            uint32_t ah[2][4], al[2][4];
            #pragma unroll
            for (int mt = 0; mt < 2; mt++) {
                int r0 = (wm + mt * 16 + (lane >> 2)) * B3_ROW + wb;
                ah[mt][0] = Ah[r0];
                ah[mt][1] = Ah[r0 + 8 * B3_ROW];
                ah[mt][2] = Ah[r0 + 4];
                ah[mt][3] = Ah[r0 + 8 * B3_ROW + 4];
                al[mt][0] = Al[r0];
                al[mt][1] = Al[r0 + 8 * B3_ROW];
                al[mt][2] = Al[r0 + 4];
                al[mt][3] = Al[r0 + 8 * B3_ROW + 4];
            }
            #pragma unroll
            for (int nt = 0; nt < NT; nt++) {
                int rb = (wn + nt * 8 + (lane >> 2)) * B3_ROW + wb;
                uint32_t bh[2] = { Bh[rb], Bh[rb + 4] };
                uint32_t bl[2] = { Bl[rb], Bl[rb + 4] };
                #pragma unroll
                for (int mt = 0; mt < 2; mt++) {
                    MMA_BF16(acc[mt][nt], ah[mt], bh);
                    MMA_BF16(acc[mt][nt], ah[mt], bl);
                    MMA_BF16(acc[mt][nt], al[mt], bh);
                }
            }
        }
        __syncthreads();
    }

    // ---- epilogue ----
    #pragma unroll
    for (int mt = 0; mt < 2; mt++) {
        int r0loc = wm + mt * 16 + (lane >> 2);
        #pragma unroll
        for (int e = 0; e < 2; e++) {
            int rowLoc = r0loc + e * 8;
            int row = mBase + rowLoc;
            if (row >= M) continue;
            if (EPI == 3) {
                int bb = z / 3, hh = z % 3;
                float dvv = aux[(long)z * NTOK + row];
                float* Cp = C + ((long)bb * NTOK + row) * EMBED + hh * HDIM;
                #pragma unroll
                for (int nt = 0; nt < NT; nt++) {
                    int c0 = nBase + wn + nt * 8 + 2 * (lane & 3);
                    #pragma unroll
                    for (int q = 0; q < 2; q++) {
                        int col = c0 + q;
                        if (col < Nreal) Cp[col] = acc[mt][nt][e * 2 + q] * dvv;
                    }
                }
            } else {
                float auxv = (EPI == 4) ? snrm[rowLoc] : 0.f;
                float* Cp = C + (long)row * Nreal;
                const float* Rp = (EPI == 2) ? res + (long)row * Nreal : nullptr;
                #pragma unroll
                for (int nt = 0; nt < NT; nt++) {
                    int c0 = nBase + wn + nt * 8 + 2 * (lane & 3);
                    #pragma unroll
                    for (int q = 0; q < 2; q++) {
                        int col = c0 + q;
                        if (col >= Nreal) continue;
                        float v = acc[mt][nt][e * 2 + q];
                        if (EPI == 4) {
                            v = __expf(v - auxv) * 0.35355339059327373f;
                        } else {
                            v += bias[col];
                            if (EPI == 1) v = 0.5f * v * (1.0f + erff(v * 0.70710678118654752f));
                            if (EPI == 2) v += Rp[col];
                        }
                        Cp[col] = v;
                    }
                }
            }
        }
    }
}

// ---------------- weight transpose ----------------
__global__ void transp_k(const float* __restrict__ in, float* __restrict__ out,
                         int K, int N, int Npad)
{
    int z = blockIdx.y;
    long idx = (long)blockIdx.x * 256 + threadIdx.x;
    if (idx >= (long)Npad * K) return;
    int n = (int)(idx / K), k = (int)(idx % K);
    out[(long)z * Npad * K + idx] =
        (n < N) ? in[(long)z * K * N + (long)k * N + n] : 0.f;
}

// ---------------- SIMT FFMA2: kvT = (pk^T @ v)^T, coalesced via smem -----
#define FMA2(acc, a, b) asm("fma.rn.f32x2 %0, %1, %2, %0;" : "+l"(acc) : "l"(a), "l"(b))
#define PACK2(dst, s)   asm("mov.b64 %0, {%1, %1};" : "=l"(dst) : "f"(s))
#define BKq 16
#define KV_SMEM (64*132*4)   // stage 64x132 floats (>= loader 25600B)

__global__ __launch_bounds__(128, 3)
void kv_gemm(const float* __restrict__ A, const float* __restrict__ Bm,
             float* __restrict__ C, long sA, long sB, long sC)
{
    // fixed: M=FEAT=256 (2 tiles of 128), N=HDIM=64, K=NTOK=197
    constexpr int M = FEAT, N = HDIM, K = NTOK;
    extern __shared__ float kvsm[];
    float* As = kvsm;                  // [2][16][132]
    float* Bs = kvsm + 2 * 16 * 132;   // [2][16][68]

    int z = blockIdx.z;
    const float* Ab = A + (long)z * sA;
    const float* Bb = Bm + (long)z * sB;
    int mBase = blockIdx.y * 128;
    int tid = threadIdx.x;
    int rt = tid >> 3, ct = tid & 7;

    unsigned long long acc[8][4];
    #pragma unroll
    for (int i = 0; i < 8; i++)
        #pragma unroll
        for (int j = 0; j < 4; j++) acc[i][j] = 0ULL;

    auto loadTile = [&](int buf, int k0) {
        // A stored [K][M] (pk): coalesced along m
        #pragma unroll
        for (int f = 0; f < 4; f++) {
            int l = tid + f * 128;
            int kk = l >> 5;
            int m4 = (l & 31) * 4;
            int gk = k0 + kk;
            float4 v = make_float4(0.f, 0.f, 0.f, 0.f);
            if (gk < K) v = *(const float4*)(Ab + (long)gk * M + mBase + m4);
            *(float4*)&As[(buf * 16 + kk) * 132 + m4] = v;
        }
        // B stored [K][N] (v)
        #pragma unroll
        for (int f = 0; f < 2; f++) {
            int l = tid + f * 128;
            int kk = l >> 4;
            int n4 = (l & 15) * 4;
            int gk = k0 + kk;
            float4 v = make_float4(0.f, 0.f, 0.f, 0.f);
            if (gk < K) v = *(const float4*)(Bb + (long)gk * N + n4);
            *(float4*)&Bs[(buf * 16 + kk) * 68 + n4] = v;
        }
    };

    int buf = 0;
    loadTile(0, 0);
    __syncthreads();
    for (int k0 = 0; k0 < K; k0 += BKq) {
        if (k0 + BKq < K) loadTile(buf ^ 1, k0 + BKq);
        #pragma unroll
        for (int kk = 0; kk < BKq; kk++) {
            const float* Ar = &As[(buf * 16 + kk) * 132 + rt * 8];
            const float* Br = &Bs[(buf * 16 + kk) * 68 + ct * 8];
            float4 a0 = *(const float4*)Ar;
            float4 a1 = *(const float4*)(Ar + 4);
            ulonglong2 b0 = *(const ulonglong2*)Br;
            ulonglong2 b1 = *(const ulonglong2*)(Br + 4);
            unsigned long long bp[4] = {b0.x, b0.y, b1.x, b1.y};
            float av[8] = {a0.x, a0.y, a0.z, a0.w, a1.x, a1.y, a1.z, a1.w};
            unsigned long long ap[8];
            #pragma unroll
            for (int i = 0; i < 8; i++) PACK2(ap[i], av[i]);
            #pragma unroll
            for (int i = 0; i < 8; i++)
                #pragma unroll
                for (int j = 0; j < 4; j++)
                    FMA2(acc[i][j], ap[i], bp[j]);
        }
        __syncthreads();
        buf ^= 1;
    }

    // ---- stage transpose into smem: stage[n][m] (64 x 132) ----
    float* stage = kvsm;   // loader memory reused; all reads done
    union F2 { unsigned long long u; float2 f; };
    #pragma unroll
    for (int i = 0; i < 8; i++) {
        int rloc = rt * 8 + i;
        #pragma unroll
        for (int j = 0; j < 4; j++) {
            int cb = ct * 8 + 2 * j;
            F2 t; t.u = acc[i][j];
            stage[cb * 132 + rloc]       = t.f.x;
            stage[(cb + 1) * 132 + rloc] = t.f.y;
        }
    }
    __syncthreads();
    // coalesced write: kvT[z][n][mBase + c]
    float* Cp = C + (long)z * sC + mBase;
    int half = tid >> 6;            // 0..1
    int c4 = (tid & 63) * 4 / 4;    // float4 index 0..63 -> col = 4*(tid&63)... 
    int c = (tid & 63) * 2;         // 2 floats per thread per row half? 
    // simpler exact mapping: 16 iterations of float4; row = 2u + half, col4 = (tid&63)
    #pragma unroll
    for (int u = 0; u < 32; u++) {
        int n = 2 * u + half;
        int col = (tid & 63) * 2;
        float2 val = *(float2*)&stage[n * 132 + col];
        *(float2*)&Cp[(long)n * FEAT + col] = val;
    }
}

// ---------------- LayerNorm (warp per row) ----------------
__global__ __launch_bounds__(256)
void ln_k(const float* __restrict__ in, long rowStride,
          const float* __restrict__ w, const float* __restrict__ b,
          float* __restrict__ out, int nRows)
{
    int warp = (blockIdx.x * 256 + threadIdx.x) >> 5;
    int lane = threadIdx.x & 31;
    if (warp >= nRows) return;
    const float* ip = in + (long)warp * rowStride;
    float2 v[3];
    #pragma unroll
    for (int j = 0; j < 3; j++)
        v[j] = *(const float2*)(ip + j * 64 + lane * 2);
    float s = v[0].x + v[0].y + v[1].x + v[1].y + v[2].x + v[2].y;
    float mu = warpSum(s) * (1.f / EMBED);
    float q = 0.f;
    #pragma unroll
    for (int j = 0; j < 3; j++) {
        v[j].x -= mu; v[j].y -= mu;
        q += v[j].x * v[j].x + v[j].y * v[j].y;
    }
    float rstd = rsqrtf(warpSum(q) * (1.f / EMBED) + 1e-5f);
    float* op = out + (long)warp * EMBED;
    #pragma unroll
    for (int j = 0; j < 3; j++) {
        int c = j * 64 + lane * 2;
        float2 wv = *(const float2*)(w + c);
        float2 bv = *(const float2*)(b + c);
        float2 o = make_float2(v[j].x * rstd * wv.x + bv.x,
                               v[j].y * rstd * wv.y + bv.y);
        *(float2*)(op + c) = o;
    }
}

__global__ __launch_bounds__(256)
void lnpos_k(const float* __restrict__ tok, const float* __restrict__ w,
             const float* __restrict__ b, const float* __restrict__ pos,
             float* __restrict__ h)
{
    int warp = (blockIdx.x * 256 + threadIdx.x) >> 5;
    int lane = threadIdx.x & 31;
    if (warp >= NPATCH * BATCH) return;
    int bb = warp / NPATCH, p = warp % NPATCH;
    const float* ip = tok + (long)warp * EMBED;
    float2 v[3];
    #pragma unroll
    for (int j = 0; j < 3; j++)
        v[j] = *(const float2*)(ip + j * 64 + lane * 2);
    float s = v[0].x + v[0].y + v[1].x + v[1].y + v[2].x + v[2].y;
    float mu = warpSum(s) * (1.f / EMBED);
    float q = 0.f;
    #pragma unroll
    for (int j = 0; j < 3; j++) {
        v[j].x -= mu; v[j].y -= mu;
        q += v[j].x * v[j].x + v[j].y * v[j].y;
    }
    float rstd = rsqrtf(warpSum(q) * (1.f / EMBED) + 1e-5f);
    float* op = h + ((long)bb * NTOK + 1 + p) * EMBED;
    const float* pp = pos + (1 + p) * EMBED;
    #pragma unroll
    for (int j = 0; j < 3; j++) {
        int c = j * 64 + lane * 2;
        float2 wv = *(const float2*)(w + c);
        float2 bv = *(const float2*)(b + c);
        float2 pv = *(const float2*)(pp + c);
        float2 o = make_float2(v[j].x * rstd * wv.x + bv.x + pv.x,
                               v[j].y * rstd * wv.y + bv.y + pv.y);
        *(float2*)(op + c) = o;
    }
}

__global__ void im2col_k(const float* __restrict__ x, float* __restrict__ px)
{
    long idx = (long)blockIdx.x * 256 + threadIdx.x;
    if (idx >= (long)NPATCH * BATCH * 768) return;
    int t = (int)(idx % 768);
    long rp = idx / 768;
    int b = (int)(rp / NPATCH), p = (int)(rp % NPATCH);
    int c = t >> 8, rem = t & 255, r = rem >> 4, col = rem & 15;
    int gy = p / 14, gx = p % 14;
    px[idx] = x[(((long)b * 3 + c) * 224 + gy * 16 + r) * 224 + gx * 16 + col];
}

__global__ void cls_k(const float* __restrict__ cls, const float* __restrict__ pos,
                      float* __restrict__ h)
{
    int b = blockIdx.x; int e = threadIdx.x;
    h[(long)b * NTOK * EMBED + e] = cls[e] + pos[e];
}

// ---------------- split: warp per (row, head) ----------------
__global__ __launch_bounds__(192)
void split_k(const float* __restrict__ qkv, float* __restrict__ qk,
             float* __restrict__ v, float* __restrict__ nrm)
{
    int wid = threadIdx.x >> 5;
    int lane = threadIdx.x & 31;
    int row = blockIdx.x * 2 + wid / 3;
    if (row >= ROWS) return;
    int hh = wid % 3;
    int b = row / NTOK, n = row % NTOK;
    const float* base = qkv + (long)row * 576 + hh * 64 + lane * 2;
    float2 qv = *(const float2*)base;
    float2 kv = *(const float2*)(base + 192);
    float2 vv = *(const float2*)(base + 384);
    long o = (((long)b * 3 + hh) * NTOK + n) * 64 + lane * 2;
    *(float2*)(qk + o) = qv;
    *(float2*)(qk + (long)BHN * HDIM + o) = kv;
    *(float2*)(v + o) = vv;
    float sq = warpSum(qv.x * qv.x + qv.y * qv.y);
    float sk = warpSum(kv.x * kv.x + kv.y * kv.y);
    if (lane == 0) {
        long r = ((long)b * 3 + hh) * NTOK + n;
        nrm[r]       = sq * 0.5f;
        nrm[BHN + r] = sk * 0.5f;
    }
}

// ---------------- ksum 2-pass ----------------
__global__ void ksum1_k(const float* __restrict__ pk, float* __restrict__ part)
{
    int z = blockIdx.x, chunk = blockIdx.y, f = threadIdx.x;
    int n0 = chunk * 29;
    int n1 = n0 + 29; if (n1 > NTOK) n1 = NTOK;
    float s = 0.f;
    for (int n = n0; n < n1; n++) s += pk[((long)z * NTOK + n) * FEAT + f];
    part[((long)chunk * ZB + z) * FEAT + f] = s;
}
__global__ void ksum2_k(const float* __restrict__ part, float* __restrict__ ks)
{
    int z = blockIdx.x, f = threadIdx.x;
    float s = 0.f;
    #pragma unroll
    for (int c = 0; c < 7; c++)
        s += part[((long)c * ZB + z) * FEAT + f];
    ks[(long)z * FEAT + f] = s;
}

// ---------------- D_inv ----------------
__global__ __launch_bounds__(256)
void dinv_k(const float* __restrict__ pq, const float* __restrict__ ks,
            float* __restrict__ dv)
{
    __shared__ float s[FEAT];
    int z = blockIdx.x;
    int tid = threadIdx.x;
    s[tid] = ks[(long)z * FEAT + tid];
    __syncthreads();
    int w = tid >> 5, l = tid & 31;
    int n = blockIdx.y * 8 + w;
    if (n < NTOK) {
        const float* p = pq + ((long)z * NTOK + n) * FEAT;
        float acc = 0.f;
        #pragma unroll
        for (int f = 0; f < FEAT / 32; f++) acc += p[l + f * 32] * s[l + f * 32];
        acc = warpSum(acc);
        if (l == 0) dv[(long)z * NTOK + n] = 1.f / acc;
    }
}

// ---------------- pool 2-pass ----------------
__global__ void pool1_k(const float* __restrict__ h, float* __restrict__ part)
{
    int b = blockIdx.x, chunk = blockIdx.y, e = threadIdx.x;
    int n0 = chunk * 8;
    int n1 = n0 + 8; if (n1 > NTOK) n1 = NTOK;
    float s = 0.f;
    for (int n = n0; n < n1; n++) s += h[((long)b * NTOK + n) * EMBED + e];
    part[((long)chunk * BATCH + b) * EMBED + e] = s;
}
__global__ void pool2_k(const float* __restrict__ part, float* __restrict__ pool)
{
    int b = blockIdx.x, e = threadIdx.x;
    float s = 0.f;
    #pragma unroll
    for (int c = 0; c < 25; c++)
        s += part[((long)c * BATCH + b) * EMBED + e];
    pool[(long)b * EMBED + e] = s * (1.f / 197.f);
}

// ---------------- host launch ----------------
extern "C" void kernel_launch(void* const* d_in, const int* in_sizes, int n_in,
                              void* d_out, int out_size)
{
    const float* x            = (const float*)d_in[0];
    const float* patch_w      = (const float*)d_in[1];
    const float* patch_b      = (const float*)d_in[2];
    const float* pe_norm_w    = (const float*)d_in[3];
    const float* pe_norm_b    = (const float*)d_in[4];
    const float* cls_token    = (const float*)d_in[5];
    const float* pos_embed    = (const float*)d_in[6];
    const float* norm1_w      = (const float*)d_in[7];
    const float* norm1_b      = (const float*)d_in[8];
    const float* qkv_w        = (const float*)d_in[9];
    const float* qkv_b        = (const float*)d_in[10];
    const float* proj_mat     = (const float*)d_in[11];
    const float* attn_proj_w  = (const float*)d_in[12];
    const float* attn_proj_b  = (const float*)d_in[13];
    const float* norm2_w      = (const float*)d_in[14];
    const float* norm2_b      = (const float*)d_in[15];
    const float* fc1_w        = (const float*)d_in[16];
    const float* fc1_b        = (const float*)d_in[17];
    const float* fc2_w        = (const float*)d_in[18];
    const float* fc2_b        = (const float*)d_in[19];
    const float* exit_w       = (const float*)d_in[20];
    const float* exit_b       = (const float*)d_in[21];
    const float* final_norm_w = (const float*)d_in[22];
    const float* final_norm_b = (const float*)d_in[23];
    const float* head_w       = (const float*)d_in[24];
    const float* head_b       = (const float*)d_in[25];
    float* out = (float*)d_out;

    float *h, *xln, *qkv, *qk, *v, *nrm, *pqk, *ks, *kspart, *dv, *kvT, *ao, *mlp;
    float *pool, *poolpart, *cls;
    float *wqkvT, *wapT, *wfc1T, *wfc2T, *wexT, *whdT;
    cudaGetSymbolAddress((void**)&h,    g_h);
    cudaGetSymbolAddress((void**)&xln,  g_xln);
    cudaGetSymbolAddress((void**)&qkv,  g_qkv);
    cudaGetSymbolAddress((void**)&qk,   g_qk);
    cudaGetSymbolAddress((void**)&v,    g_v);
    cudaGetSymbolAddress((void**)&nrm,  g_nrm);
    cudaGetSymbolAddress((void**)&pqk,  g_pqk);
    cudaGetSymbolAddress((void**)&ks,   g_ks);
    cudaGetSymbolAddress((void**)&kspart, g_kspart);
    cudaGetSymbolAddress((void**)&dv,   g_dv);
    cudaGetSymbolAddress((void**)&kvT,  g_kvT);
    cudaGetSymbolAddress((void**)&ao,   g_ao);
    cudaGetSymbolAddress((void**)&mlp,  g_mlp);
    cudaGetSymbolAddress((void**)&pool, g_pool);
    cudaGetSymbolAddress((void**)&poolpart, g_poolpart);
    cudaGetSymbolAddress((void**)&cls,  g_cls);
    cudaGetSymbolAddress((void**)&wqkvT, g_wqkvT);
    cudaGetSymbolAddress((void**)&wapT,  g_wapT);
    cudaGetSymbolAddress((void**)&wfc1T, g_wfc1T);
    cudaGetSymbolAddress((void**)&wfc2T, g_wfc2T);
    cudaGetSymbolAddress((void**)&wexT,  g_wexT);
    cudaGetSymbolAddress((void**)&whdT,  g_whdT);

    constexpr int SM128 = SmemSz<128>::BYTES;
    constexpr int SM64  = SmemSz<64>::BYTES;
    cudaFuncSetAttribute(bf3_gemm<0,128>, cudaFuncAttributeMaxDynamicSharedMemorySize, SM128);
    cudaFuncSetAttribute(bf3_gemm<1,128>, cudaFuncAttributeMaxDynamicSharedMemorySize, SM128);
    cudaFuncSetAttribute(bf3_gemm<4,128>, cudaFuncAttributeMaxDynamicSharedMemorySize, SM128);
    cudaFuncSetAttribute(bf3_gemm<0,64>,  cudaFuncAttributeMaxDynamicSharedMemorySize, SM64);
    cudaFuncSetAttribute(bf3_gemm<2,64>,  cudaFuncAttributeMaxDynamicSharedMemorySize, SM64);
    cudaFuncSetAttribute(bf3_gemm<3,64>,  cudaFuncAttributeMaxDynamicSharedMemorySize, SM64);
    cudaFuncSetAttribute(kv_gemm, cudaFuncAttributeMaxDynamicSharedMemorySize, KV_SMEM);

    const float* pk = pqk + (long)BHN * FEAT;

    // ---- weight transposes (patch_w / proj_mat are already [N][K]) ----
    transp_k<<<dim3((576*192 + 255)/256, DEPTH), 256>>>(qkv_w, wqkvT, 192, 576, 576);
    transp_k<<<dim3((192*192 + 255)/256, DEPTH), 256>>>(attn_proj_w, wapT, 192, 192, 192);
    transp_k<<<dim3((768*192 + 255)/256, DEPTH), 256>>>(fc1_w, wfc1T, 192, 768, 768);
    transp_k<<<dim3((192*768 + 255)/256, DEPTH), 256>>>(fc2_w, wfc2T, 768, 192, 192);
    transp_k<<<dim3((1024*192 + 255)/256, 3), 256>>>(exit_w, wexT, 192, 1000, 1024);
    transp_k<<<dim3((1024*192 + 255)/256, 1), 256>>>(head_w, whdT, 192, 1000, 1024);

    // ---- patch embed ----
    cls_k<<<BATCH, EMBED>>>(cls_token, pos_embed, h);
    im2col_k<<<(int)(((long)NPATCH * BATCH * 768 + 255) / 256), 256>>>(x, mlp);
    bf3_gemm<0,64><<<dim3(3, 98), 256, SM64>>>(
        mlp, patch_w, patch_b, nullptr, nullptr, ao,
        NPATCH * BATCH, EMBED, 768, 192, 0, 0);
    lnpos_k<<<(NPATCH * BATCH * 32 + 255) / 256, 256>>>(
        ao, pe_norm_w, pe_norm_b, pos_embed, h);

    int lnBlocks = (ROWS * 32 + 255) / 256;
    for (int i = 0; i < DEPTH; i++) {
        ln_k<<<lnBlocks, 256>>>(h, EMBED, norm1_w + i * EMBED, norm1_b + i * EMBED,
                                xln, ROWS);
        // qkv (BN64; N=576 exact)
        bf3_gemm<0,64><<<dim3(9, 99), 256, SM64>>>(
            xln, wqkvT + (long)i * 576 * 192, qkv_b + i * 3 * EMBED,
            nullptr, nullptr, qkv, ROWS, 3 * EMBED, EMBED, 576, 0, 0);
        split_k<<<(ROWS + 1) / 2, 192>>>(qkv, qk, v, nrm);
        // feature maps (BN128; N=256 exact)
        bf3_gemm<4,128><<<dim3(2, 591), 256, SM128>>>(
            qk, proj_mat + (long)i * FEAT * HDIM, nullptr, nullptr, nrm, pqk,
            2 * BHN, FEAT, HDIM, FEAT, 0, 0);
        ksum1_k<<<dim3(ZB, 7), FEAT>>>(pk, kspart);
        ksum2_k<<<ZB, FEAT>>>(kspart, ks);
        dinv_k<<<dim3(ZB, 25), 256>>>(pqk, ks, dv);
        // kvT = (pk^T @ v)^T  [64][256] per z (SIMT, coalesced transpose write)
        kv_gemm<<<dim3(1, 2, ZB), 128, KV_SMEM>>>(
            pk, v, kvT, (long)NTOK * FEAT, (long)NTOK * HDIM, (long)HDIM * FEAT);
        // ao = (pq @ kv) * D_inv  (bf3, batched, BN64, head scatter)
        bf3_gemm<3,64><<<dim3(1, 2, ZB), 256, SM64>>>(
            pqk, kvT, nullptr, nullptr, dv, ao,
            NTOK, HDIM, FEAT, HDIM, (long)NTOK * FEAT, (long)HDIM * FEAT);
        // attn proj + residual (BN64, exact N=192)
        bf3_gemm<2,64><<<dim3(3, 99), 256, SM64>>>(
            ao, wapT + (long)i * 192 * 192, attn_proj_b + i * EMBED,
            h, nullptr, h, ROWS, EMBED, EMBED, 192, 0, 0);
        ln_k<<<lnBlocks, 256>>>(h, EMBED, norm2_w + i * EMBED, norm2_b + i * EMBED,
                                xln, ROWS);
        // MLP
        bf3_gemm<1,128><<<dim3(6, 99), 256, SM128>>>(
            xln, wfc1T + (long)i * 768 * 192, fc1_b + i * MLPD,
            nullptr, nullptr, mlp, ROWS, MLPD, EMBED, 768, 0, 0);
        bf3_gemm<2,64><<<dim3(3, 99), 256, SM64>>>(
            mlp, wfc2T + (long)i * 192 * 768, fc2_b + i * EMBED,
            h, nullptr, h, ROWS, EMBED, MLPD, 192, 0, 0);
        if (i == 3 || i == 7 || i == 11) {
            int e = (i == 3) ? 0 : (i == 7) ? 1 : 2;
            pool1_k<<<dim3(BATCH, 25), EMBED>>>(h, poolpart);
            pool2_k<<<BATCH, EMBED>>>(poolpart, pool);
            bf3_gemm<0,128><<<dim3(8, 1), 256, SM128>>>(
                pool, wexT + (long)e * 1024 * 192, exit_b + e * NCLS,
                nullptr, nullptr, out + (long)(1 + e) * BATCH * NCLS,
                BATCH, NCLS, EMBED, 1024, 0, 0);
        }
    }

    ln_k<<<(BATCH * 32 + 255) / 256, 256>>>(
        h, (long)NTOK * EMBED, final_norm_w, final_norm_b, cls, BATCH);
    bf3_gemm<0,128><<<dim3(8, 1), 256, SM128>>>(
        cls, whdT, head_b, nullptr, nullptr, out, BATCH, NCLS, EMBED, 1024, 0, 0);
}

// round 16
// speedup vs baseline: 1.1906x; 1.0142x over previous
#include <cuda_runtime.h>
#include <cuda_bf16.h>
#include <math.h>
#include <cstdint>

// ---------------- problem constants ----------------
#define BATCH 64
#define NTOK 197
#define NPATCH 196
#define EMBED 192
#define HEADS 3
#define HDIM 64
#define FEAT 256
#define MLPD 768
#define NCLS 1000
#define DEPTH 12
#define ROWS (BATCH*NTOK)          // 12608
#define BHN  (BATCH*HEADS*NTOK)    // 37824
#define ZB   (BATCH*HEADS)         // 192

// ---------------- scratch (device globals) ----------------
__device__ float g_h   [ROWS*EMBED];
__device__ float g_xln [ROWS*EMBED];
__device__ float g_qkv [ROWS*3*EMBED];
__device__ float g_qk  [2L*BHN*HDIM];
__device__ float g_v   [BHN*HDIM];
__device__ float g_nrm [2L*BHN];
__device__ float g_pqk [2L*BHN*FEAT];
__device__ float g_ks  [ZB*FEAT];
__device__ float g_kvT [ZB*HDIM*FEAT];    // per z: [64][256]  (B operand for ao)
__device__ float g_ao  [ROWS*EMBED];
__device__ float g_mlp [ROWS*MLPD];
__device__ float g_pool[BATCH*EMBED];
__device__ float g_poolpart[25*BATCH*EMBED];
__device__ float g_cls [BATCH*EMBED];
// transposed weights [N][K] (K-major)
__device__ float g_wqkvT [DEPTH*576*192];
__device__ float g_wapT  [DEPTH*192*192];
__device__ float g_wfc1T [DEPTH*768*192];
__device__ float g_wfc2T [DEPTH*192*768];
__device__ float g_wexT  [3*1024*192];
__device__ float g_whdT  [1024*192];

__device__ __forceinline__ float warpSum(float v) {
    #pragma unroll
    for (int o = 16; o > 0; o >>= 1) v += __shfl_xor_sync(0xffffffffu, v, o);
    return v;
}

// =====================================================================
// bf16x3 mma GEMM: C[M,Nreal] = A[M,K] @ Bt^T  (optional batch over z)
// Bt stored [n][k] row-major.
// EPI: 0=bias, 1=bias+gelu, 2=bias+residual,
//      3=performer out: pre-pass dinv = 1/(A_row . ks) (aux = ks, per z),
//        epilogue scales by dinv + head scatter,
//      4=exp(acc - rowSumSq(A)/2)*64^-0.25
// =====================================================================
#define MMA_BF16(d, a, b) \
  asm volatile("mma.sync.aligned.m16n8k16.row.col.f32.bf16.bf16.f32 " \
    "{%0,%1,%2,%3}, {%4,%5,%6,%7}, {%8,%9}, {%0,%1,%2,%3};" \
    : "+f"((d)[0]), "+f"((d)[1]), "+f"((d)[2]), "+f"((d)[3]) \
    : "r"((a)[0]), "r"((a)[1]), "r"((a)[2]), "r"((a)[3]), \
      "r"((b)[0]), "r"((b)[1]))

#define PACK_BF2(w, flo, fhi) \
  asm("cvt.rn.bf16x2.f32 %0, %1, %2;" : "=r"(w) : "f"(fhi), "f"(flo))

__device__ __forceinline__ void split_pair(float x0, float x1,
                                           uint32_t& h, uint32_t& l) {
    PACK_BF2(h, x0, x1);
    float h0 = __uint_as_float(h << 16);
    float h1 = __uint_as_float(h & 0xffff0000u);
    PACK_BF2(l, x0 - h0, x1 - h1);
}

#define B3_ROW 20
#define A_TILE (128*B3_ROW)
template<int BNv> struct SmemSz {
    static constexpr int BT = BNv * B3_ROW;
    static constexpr int BYTES = (4 * A_TILE + 4 * BT) * 4;
};

template<int EPI, int BNv>
__global__ __launch_bounds__(256, 2)
void bf3_gemm(const float* __restrict__ A, const float* __restrict__ Bt,
              const float* __restrict__ bias, const float* __restrict__ res,
              const float* __restrict__ aux, float* __restrict__ C,
              int M, int Nreal, int K, long bRows, long sA, long sBt)
{
    constexpr int NT = BNv / 16;
    constexpr int BT = BNv * B3_ROW;
    extern __shared__ uint32_t smu[];
    uint32_t* Abase = smu;
    uint32_t* Bbase = smu + 4 * A_TILE;

    int z = blockIdx.z;
    const float* Ab  = A  + (long)z * sA;
    const float* Btb = Bt + (long)z * sBt;

    int tid = threadIdx.x;
    int lane = tid & 31, wid = tid >> 5;
    int wm = (wid & 3) * 32;
    int wn = (wid >> 2) * (BNv / 2);
    int mBase = blockIdx.y * 128, nBase = blockIdx.x * BNv;

    float acc[2][NT][4];
    #pragma unroll
    for (int mt = 0; mt < 2; mt++)
        #pragma unroll
        for (int nt = 0; nt < NT; nt++)
            #pragma unroll
            for (int q = 0; q < 4; q++) acc[mt][nt][q] = 0.f;

    auto ldA = [&](uint32_t* dhi, uint32_t* dlo, int k0) {
        int r = tid >> 1, half = tid & 1;
        long gr = (long)mBase + r;
        float f[16];
        if (gr < M) {
            const float4* src = (const float4*)(Ab + gr * (long)K + k0 + half * 16);
            #pragma unroll
            for (int u = 0; u < 4; u++) {
                float4 v = src[u];
                f[4*u] = v.x; f[4*u+1] = v.y; f[4*u+2] = v.z; f[4*u+3] = v.w;
            }
        } else {
            #pragma unroll
            for (int u = 0; u < 16; u++) f[u] = 0.f;
        }
        uint32_t hw[8], lw[8];
        #pragma unroll
        for (int p = 0; p < 8; p++) split_pair(f[2*p], f[2*p+1], hw[p], lw[p]);
        uint32_t* ph = dhi + r * B3_ROW + half * 8;
        uint32_t* pl = dlo + r * B3_ROW + half * 8;
        *(uint4*)ph       = make_uint4(hw[0], hw[1], hw[2], hw[3]);
        *(uint4*)(ph + 4) = make_uint4(hw[4], hw[5], hw[6], hw[7]);
        *(uint4*)pl       = make_uint4(lw[0], lw[1], lw[2], lw[3]);
        *(uint4*)(pl + 4) = make_uint4(lw[4], lw[5], lw[6], lw[7]);
    };

    auto ldB = [&](uint32_t* dhi, uint32_t* dlo, int k0) {
        if (BNv == 128) {
            int r = tid >> 1, half = tid & 1;
            long gr = (long)nBase + r;
            float f[16];
            if (gr < bRows) {
                const float4* src = (const float4*)(Btb + gr * (long)K + k0 + half * 16);
                #pragma unroll
                for (int u = 0; u < 4; u++) {
                    float4 v = src[u];
                    f[4*u] = v.x; f[4*u+1] = v.y; f[4*u+2] = v.z; f[4*u+3] = v.w;
                }
            } else {
                #pragma unroll
                for (int u = 0; u < 16; u++) f[u] = 0.f;
            }
            uint32_t hw[8], lw[8];
            #pragma unroll
            for (int p = 0; p < 8; p++) split_pair(f[2*p], f[2*p+1], hw[p], lw[p]);
            uint32_t* ph = dhi + r * B3_ROW + half * 8;
            uint32_t* pl = dlo + r * B3_ROW + half * 8;
            *(uint4*)ph       = make_uint4(hw[0], hw[1], hw[2], hw[3]);
            *(uint4*)(ph + 4) = make_uint4(hw[4], hw[5], hw[6], hw[7]);
            *(uint4*)pl       = make_uint4(lw[0], lw[1], lw[2], lw[3]);
            *(uint4*)(pl + 4) = make_uint4(lw[4], lw[5], lw[6], lw[7]);
        } else {   // BNv == 64: 4 threads per row, 8 floats each
            int r = tid >> 2, q = tid & 3;
            long gr = (long)nBase + r;
            float f[8];
            if (gr < bRows) {
                const float4* src = (const float4*)(Btb + gr * (long)K + k0 + q * 8);
                float4 v0 = src[0], v1 = src[1];
                f[0]=v0.x; f[1]=v0.y; f[2]=v0.z; f[3]=v0.w;
                f[4]=v1.x; f[5]=v1.y; f[6]=v1.z; f[7]=v1.w;
            } else {
                #pragma unroll
                for (int u = 0; u < 8; u++) f[u] = 0.f;
            }
            uint32_t hw[4], lw[4];
            #pragma unroll
            for (int p = 0; p < 4; p++) split_pair(f[2*p], f[2*p+1], hw[p], lw[p]);
            *(uint4*)(dhi + r * B3_ROW + q * 4) = make_uint4(hw[0], hw[1], hw[2], hw[3]);
            *(uint4*)(dlo + r * B3_ROW + q * 4) = make_uint4(lw[0], lw[1], lw[2], lw[3]);
        }
    };

    __shared__ float snrm[128];
    __shared__ float sks[FEAT];
    if (EPI == 4) {   // per-row sumsq/2 (K == 64 for fmap)
        int r = tid >> 1, half = tid & 1;
        long gr = (long)mBase + r;
        float ss = 0.f;
        if (gr < M) {
            const float4* src = (const float4*)(Ab + gr * (long)K + half * 32);
            #pragma unroll
            for (int u = 0; u < 8; u++) {
                float4 vv = src[u];
                ss += vv.x * vv.x + vv.y * vv.y + vv.z * vv.z + vv.w * vv.w;
            }
        }
        ss += __shfl_xor_sync(0xffffffffu, ss, 1);
        if (half == 0) snrm[r] = ss * 0.5f;
    }
    if (EPI == 3) {   // per-row dinv = 1/(A_row . ks)  (K == 256)
        sks[tid] = aux[(long)z * FEAT + tid];
        __syncthreads();
        int r = tid >> 1, half = tid & 1;
        long gr = (long)mBase + r;
        float dot = 0.f;
        if (gr < M) {
            const float4* src = (const float4*)(Ab + gr * (long)K + half * 128);
            const float* kp = sks + half * 128;
            #pragma unroll
            for (int u = 0; u < 32; u++) {
                float4 vv = src[u];
                dot += vv.x * kp[4*u] + vv.y * kp[4*u+1]
                     + vv.z * kp[4*u+2] + vv.w * kp[4*u+3];
            }
        }
        dot += __shfl_xor_sync(0xffffffffu, dot, 1);
        if (half == 0) snrm[r] = (gr < M) ? 1.f / dot : 0.f;
    }

    ldA(Abase, Abase + A_TILE, 0);
    ldB(Bbase, Bbase + BT, 0);
    __syncthreads();

    int nSteps = K / 32;
    for (int s = 0; s < nSteps; s++) {
        int buf = s & 1;
        if (s + 1 < nSteps) {
            int nb = buf ^ 1;
            ldA(Abase + nb * 2 * A_TILE, Abase + nb * 2 * A_TILE + A_TILE, (s + 1) * 32);
            ldB(Bbase + nb * 2 * BT,     Bbase + nb * 2 * BT + BT,         (s + 1) * 32);
        }
        const uint32_t* Ah = Abase + buf * 2 * A_TILE;
        const uint32_t* Al = Ah + A_TILE;
        const uint32_t* Bh = Bbase + buf * 2 * BT;
        const uint32_t* Bl = Bh + BT;
        #pragma unroll
        for (int h16 = 0; h16 < 2; h16++) {
            int wb = h16 * 8 + (lane & 3);
            uint32_t ah[2][4], al[2][4];
            #pragma unroll
            for (int mt = 0; mt < 2; mt++) {
                int r0 = (wm + mt * 16 + (lane >> 2)) * B3_ROW + wb;
                ah[mt][0] = Ah[r0];
                ah[mt][1] = Ah[r0 + 8 * B3_ROW];
                ah[mt][2] = Ah[r0 + 4];
                ah[mt][3] = Ah[r0 + 8 * B3_ROW + 4];
                al[mt][0] = Al[r0];
                al[mt][1] = Al[r0 + 8 * B3_ROW];
                al[mt][2] = Al[r0 + 4];
                al[mt][3] = Al[r0 + 8 * B3_ROW + 4];
            }
            #pragma unroll
            for (int nt = 0; nt < NT; nt++) {
                int rb = (wn + nt * 8 + (lane >> 2)) * B3_ROW + wb;
                uint32_t bh[2] = { Bh[rb], Bh[rb + 4] };
                uint32_t bl[2] = { Bl[rb], Bl[rb + 4] };
                #pragma unroll
                for (int mt = 0; mt < 2; mt++) {
                    MMA_BF16(acc[mt][nt], ah[mt], bh);
                    MMA_BF16(acc[mt][nt], ah[mt], bl);
                    MMA_BF16(acc[mt][nt], al[mt], bh);
                }
            }
        }
        __syncthreads();
    }

    // ---- epilogue ----
    #pragma unroll
    for (int mt = 0; mt < 2; mt++) {
        int r0loc = wm + mt * 16 + (lane >> 2);
        #pragma unroll
        for (int e = 0; e < 2; e++) {
            int rowLoc = r0loc + e * 8;
            int row = mBase + rowLoc;
            if (row >= M) continue;
            if (EPI == 3) {
                int bb = z / 3, hh = z % 3;
                float dvv = snrm[rowLoc];
                float* Cp = C + ((long)bb * NTOK + row) * EMBED + hh * HDIM;
                #pragma unroll
                for (int nt = 0; nt < NT; nt++) {
                    int c0 = nBase + wn + nt * 8 + 2 * (lane & 3);
                    #pragma unroll
                    for (int q = 0; q < 2; q++) {
                        int col = c0 + q;
                        if (col < Nreal) Cp[col] = acc[mt][nt][e * 2 + q] * dvv;
                    }
                }
            } else {
                float auxv = (EPI == 4) ? snrm[rowLoc] : 0.f;
                float* Cp = C + (long)row * Nreal;
                const float* Rp = (EPI == 2) ? res + (long)row * Nreal : nullptr;
                #pragma unroll
                for (int nt = 0; nt < NT; nt++) {
                    int c0 = nBase + wn + nt * 8 + 2 * (lane & 3);
                    #pragma unroll
                    for (int q = 0; q < 2; q++) {
                        int col = c0 + q;
                        if (col >= Nreal) continue;
                        float v = acc[mt][nt][e * 2 + q];
                        if (EPI == 4) {
                            v = __expf(v - auxv) * 0.35355339059327373f;
                        } else {
                            v += bias[col];
                            if (EPI == 1) v = 0.5f * v * (1.0f + erff(v * 0.70710678118654752f));
                            if (EPI == 2) v += Rp[col];
                        }
                        Cp[col] = v;
                    }
                }
            }
        }
    }
}

// ---------------- weight transpose ----------------
__global__ void transp_k(const float* __restrict__ in, float* __restrict__ out,
                         int K, int N, int Npad)
{
    int z = blockIdx.y;
    long idx = (long)blockIdx.x * 256 + threadIdx.x;
    if (idx >= (long)Npad * K) return;
    int n = (int)(idx / K), k = (int)(idx % K);
    out[(long)z * Npad * K + idx] =
        (n < N) ? in[(long)z * K * N + (long)k * N + n] : 0.f;
}

// ---- SIMT FFMA2: kvT = (pk^T @ v)^T (smem-staged) + ks colsum fused ----
#define FMA2(acc, a, b) asm("fma.rn.f32x2 %0, %1, %2, %0;" : "+l"(acc) : "l"(a), "l"(b))
#define PACK2(dst, s)   asm("mov.b64 %0, {%1, %1};" : "=l"(dst) : "f"(s))
#define BKq 16
#define KV_SMEM (64*132*4)

__global__ __launch_bounds__(128, 3)
void kv_gemm(const float* __restrict__ A, const float* __restrict__ Bm,
             float* __restrict__ C, float* __restrict__ ksOut,
             long sA, long sB, long sC)
{
    // fixed: M=FEAT=256 (2 tiles of 128), N=HDIM=64, K=NTOK=197
    constexpr int M = FEAT, N = HDIM, K = NTOK;
    extern __shared__ float kvsm[];
    float* As = kvsm;                  // [2][16][132]
    float* Bs = kvsm + 2 * 16 * 132;   // [2][16][68]

    int z = blockIdx.z;
    const float* Ab = A + (long)z * sA;
    const float* Bb = Bm + (long)z * sB;
    int mBase = blockIdx.y * 128;
    int tid = threadIdx.x;
    int rt = tid >> 3, ct = tid & 7;

    unsigned long long acc[8][4];
    #pragma unroll
    for (int i = 0; i < 8; i++)
        #pragma unroll
        for (int j = 0; j < 4; j++) acc[i][j] = 0ULL;
    float colsum[8];
    #pragma unroll
    for (int i = 0; i < 8; i++) colsum[i] = 0.f;

    auto loadTile = [&](int buf, int k0) {
        #pragma unroll
        for (int f = 0; f < 4; f++) {
            int l = tid + f * 128;
            int kk = l >> 5;
            int m4 = (l & 31) * 4;
            int gk = k0 + kk;
            float4 v = make_float4(0.f, 0.f, 0.f, 0.f);
            if (gk < K) v = *(const float4*)(Ab + (long)gk * M + mBase + m4);
            *(float4*)&As[(buf * 16 + kk) * 132 + m4] = v;
        }
        #pragma unroll
        for (int f = 0; f < 2; f++) {
            int l = tid + f * 128;
            int kk = l >> 4;
            int n4 = (l & 15) * 4;
            int gk = k0 + kk;
            float4 v = make_float4(0.f, 0.f, 0.f, 0.f);
            if (gk < K) v = *(const float4*)(Bb + (long)gk * N + n4);
            *(float4*)&Bs[(buf * 16 + kk) * 68 + n4] = v;
        }
    };

    int buf = 0;
    loadTile(0, 0);
    __syncthreads();
    for (int k0 = 0; k0 < K; k0 += BKq) {
        if (k0 + BKq < K) loadTile(buf ^ 1, k0 + BKq);
        #pragma unroll
        for (int kk = 0; kk < BKq; kk++) {
            const float* Ar = &As[(buf * 16 + kk) * 132 + rt * 8];
            const float* Br = &Bs[(buf * 16 + kk) * 68 + ct * 8];
            float4 a0 = *(const float4*)Ar;
            float4 a1 = *(const float4*)(Ar + 4);
            ulonglong2 b0 = *(const ulonglong2*)Br;
            ulonglong2 b1 = *(const ulonglong2*)(Br + 4);
            unsigned long long bp[4] = {b0.x, b0.y, b1.x, b1.y};
            float av[8] = {a0.x, a0.y, a0.z, a0.w, a1.x, a1.y, a1.z, a1.w};
            if (ct == 0) {
                #pragma unroll
                for (int i = 0; i < 8; i++) colsum[i] += av[i];
            }
            unsigned long long ap[8];
            #pragma unroll
            for (int i = 0; i < 8; i++) PACK2(ap[i], av[i]);
            #pragma unroll
            for (int i = 0; i < 8; i++)
                #pragma unroll
                for (int j = 0; j < 4; j++)
                    FMA2(acc[i][j], ap[i], bp[j]);
        }
        __syncthreads();
        buf ^= 1;
    }

    // ks output (fused k_cumsum)
    if (ct == 0) {
        float* kp = ksOut + (long)z * FEAT + mBase + rt * 8;
        #pragma unroll
        for (int i = 0; i < 8; i++) kp[i] = colsum[i];
    }

    // ---- stage transpose into smem: stage[n][m] (64 x 132) ----
    float* stage = kvsm;
    union F2 { unsigned long long u; float2 f; };
    #pragma unroll
    for (int i = 0; i < 8; i++) {
        int rloc = rt * 8 + i;
        #pragma unroll
        for (int j = 0; j < 4; j++) {
            int cb = ct * 8 + 2 * j;
            F2 t; t.u = acc[i][j];
            stage[cb * 132 + rloc]       = t.f.x;
            stage[(cb + 1) * 132 + rloc] = t.f.y;
        }
    }
    __syncthreads();
    float* Cp = C + (long)z * sC + mBase;
    int half = tid >> 6;
    #pragma unroll
    for (int u = 0; u < 32; u++) {
        int n = 2 * u + half;
        int col = (tid & 63) * 2;
        float2 val = *(float2*)&stage[n * 132 + col];
        *(float2*)&Cp[(long)n * FEAT + col] = val;
    }
}

// ---------------- LayerNorm (warp per row) ----------------
__global__ __launch_bounds__(256)
void ln_k(const float* __restrict__ in, long rowStride,
          const float* __restrict__ w, const float* __restrict__ b,
          float* __restrict__ out, int nRows)
{
    int warp = (blockIdx.x * 256 + threadIdx.x) >> 5;
    int lane = threadIdx.x & 31;
    if (warp >= nRows) return;
    const float* ip = in + (long)warp * rowStride;
    float2 v[3];
    #pragma unroll
    for (int j = 0; j < 3; j++)
        v[j] = *(const float2*)(ip + j * 64 + lane * 2);
    float s = v[0].x + v[0].y + v[1].x + v[1].y + v[2].x + v[2].y;
    float mu = warpSum(s) * (1.f / EMBED);
    float q = 0.f;
    #pragma unroll
    for (int j = 0; j < 3; j++) {
        v[j].x -= mu; v[j].y -= mu;
        q += v[j].x * v[j].x + v[j].y * v[j].y;
    }
    float rstd = rsqrtf(warpSum(q) * (1.f / EMBED) + 1e-5f);
    float* op = out + (long)warp * EMBED;
    #pragma unroll
    for (int j = 0; j < 3; j++) {
        int c = j * 64 + lane * 2;
        float2 wv = *(const float2*)(w + c);
        float2 bv = *(const float2*)(b + c);
        float2 o = make_float2(v[j].x * rstd * wv.x + bv.x,
                               v[j].y * rstd * wv.y + bv.y);
        *(float2*)(op + c) = o;
    }
}

__global__ __launch_bounds__(256)
void lnpos_k(const float* __restrict__ tok, const float* __restrict__ w,
             const float* __restrict__ b, const float* __restrict__ pos,
             float* __restrict__ h)
{
    int warp = (blockIdx.x * 256 + threadIdx.x) >> 5;
    int lane = threadIdx.x & 31;
    if (warp >= NPATCH * BATCH) return;
    int bb = warp / NPATCH, p = warp % NPATCH;
    const float* ip = tok + (long)warp * EMBED;
    float2 v[3];
    #pragma unroll
    for (int j = 0; j < 3; j++)
        v[j] = *(const float2*)(ip + j * 64 + lane * 2);
    float s = v[0].x + v[0].y + v[1].x + v[1].y + v[2].x + v[2].y;
    float mu = warpSum(s) * (1.f / EMBED);
    float q = 0.f;
    #pragma unroll
    for (int j = 0; j < 3; j++) {
        v[j].x -= mu; v[j].y -= mu;
        q += v[j].x * v[j].x + v[j].y * v[j].y;
    }
    float rstd = rsqrtf(warpSum(q) * (1.f / EMBED) + 1e-5f);
    float* op = h + ((long)bb * NTOK + 1 + p) * EMBED;
    const float* pp = pos + (1 + p) * EMBED;
    #pragma unroll
    for (int j = 0; j < 3; j++) {
        int c = j * 64 + lane * 2;
        float2 wv = *(const float2*)(w + c);
        float2 bv = *(const float2*)(b + c);
        float2 pv = *(const float2*)(pp + c);
        float2 o = make_float2(v[j].x * rstd * wv.x + bv.x + pv.x,
                               v[j].y * rstd * wv.y + bv.y + pv.y);
        *(float2*)(op + c) = o;
    }
}

__global__ void im2col_k(const float* __restrict__ x, float* __restrict__ px)
{
    long idx = (long)blockIdx.x * 256 + threadIdx.x;
    if (idx >= (long)NPATCH * BATCH * 768) return;
    int t = (int)(idx % 768);
    long rp = idx / 768;
    int b = (int)(rp / NPATCH), p = (int)(rp % NPATCH);
    int c = t >> 8, rem = t & 255, r = rem >> 4, col = rem & 15;
    int gy = p / 14, gx = p % 14;
    px[idx] = x[(((long)b * 3 + c) * 224 + gy * 16 + r) * 224 + gx * 16 + col];
}

__global__ void cls_k(const float* __restrict__ cls, const float* __restrict__ pos,
                      float* __restrict__ h)
{
    int b = blockIdx.x; int e = threadIdx.x;
    h[(long)b * NTOK * EMBED + e] = cls[e] + pos[e];
}

// ---------------- split: warp per (row, head) ----------------
__global__ __launch_bounds__(192)
void split_k(const float* __restrict__ qkv, float* __restrict__ qk,
             float* __restrict__ v, float* __restrict__ nrm)
{
    int wid = threadIdx.x >> 5;
    int lane = threadIdx.x & 31;
    int row = blockIdx.x * 2 + wid / 3;
    if (row >= ROWS) return;
    int hh = wid % 3;
    int b = row / NTOK, n = row % NTOK;
    const float* base = qkv + (long)row * 576 + hh * 64 + lane * 2;
    float2 qv = *(const float2*)base;
    float2 kv = *(const float2*)(base + 192);
    float2 vv = *(const float2*)(base + 384);
    long o = (((long)b * 3 + hh) * NTOK + n) * 64 + lane * 2;
    *(float2*)(qk + o) = qv;
    *(float2*)(qk + (long)BHN * HDIM + o) = kv;
    *(float2*)(v + o) = vv;
    float sq = warpSum(qv.x * qv.x + qv.y * qv.y);
    float sk = warpSum(kv.x * kv.x + kv.y * kv.y);
    if (lane == 0) {
        long r = ((long)b * 3 + hh) * NTOK + n;
        nrm[r]       = sq * 0.5f;
        nrm[BHN + r] = sk * 0.5f;
    }
}

// ---------------- pool 2-pass ----------------
__global__ void pool1_k(const float* __restrict__ h, float* __restrict__ part)
{
    int b = blockIdx.x, chunk = blockIdx.y, e = threadIdx.x;
    int n0 = chunk * 8;
    int n1 = n0 + 8; if (n1 > NTOK) n1 = NTOK;
    float s = 0.f;
    for (int n = n0; n < n1; n++) s += h[((long)b * NTOK + n) * EMBED + e];
    part[((long)chunk * BATCH + b) * EMBED + e] = s;
}
__global__ void pool2_k(const float* __restrict__ part, float* __restrict__ pool)
{
    int b = blockIdx.x, e = threadIdx.x;
    float s = 0.f;
    #pragma unroll
    for (int c = 0; c < 25; c++)
        s += part[((long)c * BATCH + b) * EMBED + e];
    pool[(long)b * EMBED + e] = s * (1.f / 197.f);
}

// ---------------- host launch ----------------
extern "C" void kernel_launch(void* const* d_in, const int* in_sizes, int n_in,
                              void* d_out, int out_size)
{
    const float* x            = (const float*)d_in[0];
    const float* patch_w      = (const float*)d_in[1];
    const float* patch_b      = (const float*)d_in[2];
    const float* pe_norm_w    = (const float*)d_in[3];
    const float* pe_norm_b    = (const float*)d_in[4];
    const float* cls_token    = (const float*)d_in[5];
    const float* pos_embed    = (const float*)d_in[6];
    const float* norm1_w      = (const float*)d_in[7];
    const float* norm1_b      = (const float*)d_in[8];
    const float* qkv_w        = (const float*)d_in[9];
    const float* qkv_b        = (const float*)d_in[10];
    const float* proj_mat     = (const float*)d_in[11];
    const float* attn_proj_w  = (const float*)d_in[12];
    const float* attn_proj_b  = (const float*)d_in[13];
    const float* norm2_w      = (const float*)d_in[14];
    const float* norm2_b      = (const float*)d_in[15];
    const float* fc1_w        = (const float*)d_in[16];
    const float* fc1_b        = (const float*)d_in[17];
    const float* fc2_w        = (const float*)d_in[18];
    const float* fc2_b        = (const float*)d_in[19];
    const float* exit_w       = (const float*)d_in[20];
    const float* exit_b       = (const float*)d_in[21];
    const float* final_norm_w = (const float*)d_in[22];
    const float* final_norm_b = (const float*)d_in[23];
    const float* head_w       = (const float*)d_in[24];
    const float* head_b       = (const float*)d_in[25];
    float* out = (float*)d_out;

    float *h, *xln, *qkv, *qk, *v, *nrm, *pqk, *ks, *kvT, *ao, *mlp;
    float *pool, *poolpart, *cls;
    float *wqkvT, *wapT, *wfc1T, *wfc2T, *wexT, *whdT;
    cudaGetSymbolAddress((void**)&h,    g_h);
    cudaGetSymbolAddress((void**)&xln,  g_xln);
    cudaGetSymbolAddress((void**)&qkv,  g_qkv);
    cudaGetSymbolAddress((void**)&qk,   g_qk);
    cudaGetSymbolAddress((void**)&v,    g_v);
    cudaGetSymbolAddress((void**)&nrm,  g_nrm);
    cudaGetSymbolAddress((void**)&pqk,  g_pqk);
    cudaGetSymbolAddress((void**)&ks,   g_ks);
    cudaGetSymbolAddress((void**)&kvT,  g_kvT);
    cudaGetSymbolAddress((void**)&ao,   g_ao);
    cudaGetSymbolAddress((void**)&mlp,  g_mlp);
    cudaGetSymbolAddress((void**)&pool, g_pool);
    cudaGetSymbolAddress((void**)&poolpart, g_poolpart);
    cudaGetSymbolAddress((void**)&cls,  g_cls);
    cudaGetSymbolAddress((void**)&wqkvT, g_wqkvT);
    cudaGetSymbolAddress((void**)&wapT,  g_wapT);
    cudaGetSymbolAddress((void**)&wfc1T, g_wfc1T);
    cudaGetSymbolAddress((void**)&wfc2T, g_wfc2T);
    cudaGetSymbolAddress((void**)&wexT,  g_wexT);
    cudaGetSymbolAddress((void**)&whdT,  g_whdT);

    constexpr int SM128 = SmemSz<128>::BYTES;
    constexpr int SM64  = SmemSz<64>::BYTES;
    cudaFuncSetAttribute(bf3_gemm<0,128>, cudaFuncAttributeMaxDynamicSharedMemorySize, SM128);
    cudaFuncSetAttribute(bf3_gemm<1,128>, cudaFuncAttributeMaxDynamicSharedMemorySize, SM128);
    cudaFuncSetAttribute(bf3_gemm<4,128>, cudaFuncAttributeMaxDynamicSharedMemorySize, SM128);
    cudaFuncSetAttribute(bf3_gemm<0,64>,  cudaFuncAttributeMaxDynamicSharedMemorySize, SM64);
    cudaFuncSetAttribute(bf3_gemm<2,64>,  cudaFuncAttributeMaxDynamicSharedMemorySize, SM64);
    cudaFuncSetAttribute(bf3_gemm<3,64>,  cudaFuncAttributeMaxDynamicSharedMemorySize, SM64);
    cudaFuncSetAttribute(kv_gemm, cudaFuncAttributeMaxDynamicSharedMemorySize, KV_SMEM);

    const float* pk = pqk + (long)BHN * FEAT;

    // ---- weight transposes (patch_w / proj_mat are already [N][K]) ----
    transp_k<<<dim3((576*192 + 255)/256, DEPTH), 256>>>(qkv_w, wqkvT, 192, 576, 576);
    transp_k<<<dim3((192*192 + 255)/256, DEPTH), 256>>>(attn_proj_w, wapT, 192, 192, 192);
    transp_k<<<dim3((768*192 + 255)/256, DEPTH), 256>>>(fc1_w, wfc1T, 192, 768, 768);
    transp_k<<<dim3((192*768 + 255)/256, DEPTH), 256>>>(fc2_w, wfc2T, 768, 192, 192);
    transp_k<<<dim3((1024*192 + 255)/256, 3), 256>>>(exit_w, wexT, 192, 1000, 1024);
    transp_k<<<dim3((1024*192 + 255)/256, 1), 256>>>(head_w, whdT, 192, 1000, 1024);

    // ---- patch embed ----
    cls_k<<<BATCH, EMBED>>>(cls_token, pos_embed, h);
    im2col_k<<<(int)(((long)NPATCH * BATCH * 768 + 255) / 256), 256>>>(x, mlp);
    bf3_gemm<0,64><<<dim3(3, 98), 256, SM64>>>(
        mlp, patch_w, patch_b, nullptr, nullptr, ao,
        NPATCH * BATCH, EMBED, 768, 192, 0, 0);
    lnpos_k<<<(NPATCH * BATCH * 32 + 255) / 256, 256>>>(
        ao, pe_norm_w, pe_norm_b, pos_embed, h);

    int lnBlocks = (ROWS * 32 + 255) / 256;
    for (int i = 0; i < DEPTH; i++) {
        ln_k<<<lnBlocks, 256>>>(h, EMBED, norm1_w + i * EMBED, norm1_b + i * EMBED,
                                xln, ROWS);
        // qkv (BN64; N=576 exact)
        bf3_gemm<0,64><<<dim3(9, 99), 256, SM64>>>(
            xln, wqkvT + (long)i * 576 * 192, qkv_b + i * 3 * EMBED,
            nullptr, nullptr, qkv, ROWS, 3 * EMBED, EMBED, 576, 0, 0);
        split_k<<<(ROWS + 1) / 2, 192>>>(qkv, qk, v, nrm);
        // feature maps (BN128; N=256 exact)
        bf3_gemm<4,128><<<dim3(2, 591), 256, SM128>>>(
            qk, proj_mat + (long)i * FEAT * HDIM, nullptr, nullptr, nrm, pqk,
            2 * BHN, FEAT, HDIM, FEAT, 0, 0);
        // kvT = (pk^T @ v)^T  [64][256] per z; ks colsum fused
        kv_gemm<<<dim3(1, 2, ZB), 128, KV_SMEM>>>(
            pk, v, kvT, ks, (long)NTOK * FEAT, (long)NTOK * HDIM, (long)HDIM * FEAT);
        // ao = (pq @ kv) * D_inv  (bf3, batched; dinv computed in pre-pass)
        bf3_gemm<3,64><<<dim3(1, 2, ZB), 256, SM64>>>(
            pqk, kvT, nullptr, nullptr, ks, ao,
            NTOK, HDIM, FEAT, HDIM, (long)NTOK * FEAT, (long)HDIM * FEAT);
        // attn proj + residual (BN64, exact N=192)
        bf3_gemm<2,64><<<dim3(3, 99), 256, SM64>>>(
            ao, wapT + (long)i * 192 * 192, attn_proj_b + i * EMBED,
            h, nullptr, h, ROWS, EMBED, EMBED, 192, 0, 0);
        ln_k<<<lnBlocks, 256>>>(h, EMBED, norm2_w + i * EMBED, norm2_b + i * EMBED,
                                xln, ROWS);
        // MLP
        bf3_gemm<1,128><<<dim3(6, 99), 256, SM128>>>(
            xln, wfc1T + (long)i * 768 * 192, fc1_b + i * MLPD,
            nullptr, nullptr, mlp, ROWS, MLPD, EMBED, 768, 0, 0);
        bf3_gemm<2,64><<<dim3(3, 99), 256, SM64>>>(
            mlp, wfc2T + (long)i * 192 * 768, fc2_b + i * EMBED,
            h, nullptr, h, ROWS, EMBED, MLPD, 192, 0, 0);
        if (i == 3 || i == 7 || i == 11) {
            int e = (i == 3) ? 0 : (i == 7) ? 1 : 2;
            pool1_k<<<dim3(BATCH, 25), EMBED>>>(h, poolpart);
            pool2_k<<<BATCH, EMBED>>>(poolpart, pool);
            bf3_gemm<0,128><<<dim3(8, 1), 256, SM128>>>(
                pool, wexT + (long)e * 1024 * 192, exit_b + e * NCLS,
                nullptr, nullptr, out + (long)(1 + e) * BATCH * NCLS,
                BATCH, NCLS, EMBED, 1024, 0, 0);
        }
    }

    ln_k<<<(BATCH * 32 + 255) / 256, 256>>>(
        h, (long)NTOK * EMBED, final_norm_w, final_norm_b, cls, BATCH);
    bf3_gemm<0,128><<<dim3(8, 1), 256, SM128>>>(
        cls, whdT, head_b, nullptr, nullptr, out, BATCH, NCLS, EMBED, 1024, 0, 0);
}